// round 2
// baseline (speedup 1.0000x reference)
#include <cuda_runtime.h>
#include <math.h>

// Problem constants
#define BB   4
#define TT   4096
#define DD   1024
#define HH   16
#define HDIM 64
#define KK   32
#define D3   (3*DD)
#define BH   (BB*HH)

// ---------------- scratch (device globals; no allocation) ----------------
__device__ float g_qkv[(size_t)BB*TT*D3];          // (B,T,3D)  201MB
__device__ float g_spec[3][BH*KK*HDIM];            // q/k/v spectral (B,H,K,HD)
__device__ float g_qm_part[BH][32][HDIM];          // partial sums for qm
__device__ float g_resp[BH*KK];                    // soliton response
__device__ float g_rv[BH*KK*HDIM];                 // response * v_spec
__device__ float g_outpre[(size_t)BB*TT*DD];       // pre-W_out output  67MB

// ---------------- generic NT GEMM: C(M,N) = A(M,K) * B(N,K)^T ----------------
// 128x128 tile, BK=8, 256 threads, 8x8 per thread. M%128==0, N%128==0, K%8==0.
__device__ __forceinline__ void gemm_nt_body(const float* __restrict__ A,
                                             const float* __restrict__ B,
                                             float* __restrict__ C,
                                             int M, int N, int K)
{
    __shared__ float As[8][128];
    __shared__ float Bs[8][128];
    const int tid = threadIdx.x;
    const int bm  = blockIdx.y * 128;
    const int bn  = blockIdx.x * 128;
    const int tx  = tid & 15;        // 0..15 (N dir)
    const int ty  = tid >> 4;        // 0..15 (M dir)
    const int lr  = tid >> 1;        // 0..127 row within tile
    const int lc  = (tid & 1) << 2;  // 0 or 4

    const float* Ap = A + (size_t)(bm + lr) * K + lc;
    const float* Bp = B + (size_t)(bn + lr) * K + lc;

    float acc[8][8];
#pragma unroll
    for (int i = 0; i < 8; i++)
#pragma unroll
        for (int j = 0; j < 8; j++) acc[i][j] = 0.f;

    for (int k0 = 0; k0 < K; k0 += 8) {
        float4 av = *(const float4*)(Ap + k0);
        float4 bv = *(const float4*)(Bp + k0);
        As[lc+0][lr] = av.x; As[lc+1][lr] = av.y; As[lc+2][lr] = av.z; As[lc+3][lr] = av.w;
        Bs[lc+0][lr] = bv.x; Bs[lc+1][lr] = bv.y; Bs[lc+2][lr] = bv.z; Bs[lc+3][lr] = bv.w;
        __syncthreads();
#pragma unroll
        for (int kk = 0; kk < 8; kk++) {
            float ra[8], rb[8];
            *(float4*)(ra)   = *(const float4*)(&As[kk][ty*8]);
            *(float4*)(ra+4) = *(const float4*)(&As[kk][ty*8+4]);
            *(float4*)(rb)   = *(const float4*)(&Bs[kk][tx*8]);
            *(float4*)(rb+4) = *(const float4*)(&Bs[kk][tx*8+4]);
#pragma unroll
            for (int i = 0; i < 8; i++)
#pragma unroll
                for (int j = 0; j < 8; j++)
                    acc[i][j] += ra[i] * rb[j];
        }
        __syncthreads();
    }
#pragma unroll
    for (int i = 0; i < 8; i++) {
        float* Cp = C + (size_t)(bm + ty*8 + i) * N + bn + tx*8;
        *(float4*)(Cp)   = make_float4(acc[i][0], acc[i][1], acc[i][2], acc[i][3]);
        *(float4*)(Cp+4) = make_float4(acc[i][4], acc[i][5], acc[i][6], acc[i][7]);
    }
}

__global__ void __launch_bounds__(256)
gemm1_kernel(const float* __restrict__ x, const float* __restrict__ Wqkv) {
    gemm_nt_body(x, Wqkv, g_qkv, BB*TT, D3, DD);
}

__global__ void __launch_bounds__(256)
gemm2_kernel(const float* __restrict__ Wout, float* __restrict__ C) {
    gemm_nt_body(g_outpre, Wout, C, BB*TT, DD, DD);
}

// ---------------- qm partial reduction: mean of q over T ----------------
// grid (BH, 32), 64 threads. Each block sums 128 t-rows.
__global__ void qmean_part_kernel() {
    const int bh = blockIdx.x;
    const int sp = blockIdx.y;
    const int b  = bh >> 4, h = bh & 15;
    const int d  = threadIdx.x;
    const float* base = g_qkv + ((size_t)b*TT + sp*128) * D3 + h*HDIM + d;
    float s = 0.f;
#pragma unroll 8
    for (int t = 0; t < 128; t++) s += base[(size_t)t * D3];
    g_qm_part[bh][sp][d] = s;
}

// ---------------- pulse widths: silu MLP per (b,h) ----------------
// grid BH, 64 threads.
__global__ void pulse_kernel(const float* __restrict__ W1, const float* __restrict__ b1,
                             const float* __restrict__ W2, const float* __restrict__ b2,
                             float* __restrict__ out_pw) {
    __shared__ float qm[HDIM];
    __shared__ float h1[32];
    const int bh = blockIdx.x;
    const int d  = threadIdx.x;
    float s = 0.f;
#pragma unroll
    for (int sp = 0; sp < 32; sp++) s += g_qm_part[bh][sp][d];
    qm[d] = s * (1.0f / (float)TT);
    __syncthreads();
    if (d < 32) {
        float a = b1[d];
#pragma unroll
        for (int j = 0; j < HDIM; j++) a += qm[j] * W1[d*HDIM + j];
        h1[d] = a / (1.f + expf(-a));      // silu
    }
    __syncthreads();
    if (d == 0) {
        float a = b2[0];
#pragma unroll
        for (int j = 0; j < 32; j++) a += h1[j] * W2[j];
        float spl = (a > 20.f) ? a : log1pf(expf(a));  // softplus
        out_pw[bh] = 4.0f + spl;
    }
}

// ---------------- spectral projection: spec[s][b,h,k,d] = sum_t qkv_s * basis ----
// grid (BH, 3), 128 threads. Per block computes a (32 x 64) output, looping T in
// chunks of 32. Each thread holds a 4(k) x 4(d) accumulator patch.
__global__ void __launch_bounds__(128)
spec_kernel(const float* __restrict__ basis) {
    __shared__ float qs[32][64];   // (tt, d)
    __shared__ float sb[32][32];   // (tt, k)
    const int bh  = blockIdx.x;
    const int sel = blockIdx.y;
    const int b   = bh >> 4, h = bh & 15;
    const int tid = threadIdx.x;
    const int d0  = (tid & 15) * 4;  // 0..60
    const int kq  = tid >> 4;        // 0..7

    float acc[4][4];
#pragma unroll
    for (int i = 0; i < 4; i++)
#pragma unroll
        for (int j = 0; j < 4; j++) acc[i][j] = 0.f;

    for (int t0 = 0; t0 < TT; t0 += 32) {
        // load q tile: 32 rows x 64 cols = 512 float4
        const size_t rowbase = ((size_t)b*TT + t0) * D3 + sel*DD + h*HDIM;
#pragma unroll
        for (int i = 0; i < 4; i++) {
            int f   = tid + 128*i;         // 0..511
            int row = f >> 4;
            int c4  = f & 15;
            ((float4*)&qs[0][0])[f] = *(const float4*)(g_qkv + rowbase + (size_t)row*D3 + c4*4);
        }
        // load basis tile: 32 rows x 32 cols = contiguous 1024 floats = 256 float4
        const float4* bsrc = (const float4*)(basis + ((size_t)b*TT + t0) * KK);
        ((float4*)&sb[0][0])[tid]       = bsrc[tid];
        ((float4*)&sb[0][0])[tid + 128] = bsrc[tid + 128];
        __syncthreads();
#pragma unroll
        for (int tt = 0; tt < 32; tt++) {
            float4 qv = *(const float4*)(&qs[tt][d0]);
            float sv0 = sb[tt][kq];
            float sv1 = sb[tt][kq + 8];
            float sv2 = sb[tt][kq + 16];
            float sv3 = sb[tt][kq + 24];
            acc[0][0] += sv0*qv.x; acc[0][1] += sv0*qv.y; acc[0][2] += sv0*qv.z; acc[0][3] += sv0*qv.w;
            acc[1][0] += sv1*qv.x; acc[1][1] += sv1*qv.y; acc[1][2] += sv1*qv.z; acc[1][3] += sv1*qv.w;
            acc[2][0] += sv2*qv.x; acc[2][1] += sv2*qv.y; acc[2][2] += sv2*qv.z; acc[2][3] += sv2*qv.w;
            acc[3][0] += sv3*qv.x; acc[3][1] += sv3*qv.y; acc[3][2] += sv3*qv.z; acc[3][3] += sv3*qv.w;
        }
        __syncthreads();
    }
#pragma unroll
    for (int jk = 0; jk < 4; jk++) {
        int k = kq + 8*jk;
        *(float4*)(&g_spec[sel][((size_t)bh*KK + k)*HDIM + d0]) =
            make_float4(acc[jk][0], acc[jk][1], acc[jk][2], acc[jk][3]);
    }
}

// ---------------- attn + filter + scalar soliton ODE ----------------
// stim is constant across HD -> the ODE is scalar per (b,h,k).
__global__ void soliton_kernel(const float* __restrict__ sfilt,
                               const float* __restrict__ pa, const float* __restrict__ pb,
                               float* __restrict__ out_resp) {
    const int bh = blockIdx.x;
    const int h  = bh & 15;
    const int k  = threadIdx.x;   // 0..31
    const float* qsp = &g_spec[0][((size_t)bh*KK + k)*HDIM];
    const float* ksp = &g_spec[1][((size_t)bh*KK + k)*HDIM];
    float dot = 0.f;
#pragma unroll
    for (int d = 0; d < HDIM; d++) dot += qsp[d]*ksp[d];
    float filt = 1.f / (1.f + expf(-sfilt[h*KK + k]));
    float s = dot * 0.125f * filt;       // / sqrt(64)

    float scale = fmaxf(fabsf(s), 1e-6f);
    float sn = s / scale;
    float I  = (fabsf(s) > 0.5f) ? sn : 0.1f*sn;
    const float a = *pa, b = *pb;
    const float dt = 0.2f;
    float v = 0.f, w = 0.f;
#pragma unroll
    for (int it = 0; it < 5; it++) {
        float dv = v - v*v*v*(1.f/3.f) - w + I;
        float dw = (v + a - b*w) * 10.f;   // / TAU
        v = fminf(fmaxf(v + dt*dv, -3.f), 3.f);
        w = fminf(fmaxf(w + dt*dw, -3.f), 3.f);
    }
    float r = v * scale;
    g_resp[bh*KK + k]   = r;
    out_resp[bh*KK + k] = r;
}

// ---------------- rv = response * v_spec ----------------
__global__ void rv_kernel() {
    int i = blockIdx.x * 256 + threadIdx.x;   // 131072 total
    g_rv[i] = g_resp[i >> 6] * g_spec[2][i];
}

// ---------------- synthesis: outpre[b,t,h*64+d] = sum_k basis[b,t,k]*rv[b,h,k,d] --
// grid (T/64, BH), 256 threads, 64x64 output tile per block.
__global__ void __launch_bounds__(256)
synth_kernel(const float* __restrict__ basis) {
    __shared__ float srv[KK][HDIM];   // 8KB
    __shared__ float sbas[64][KK];    // 8KB
    const int bh = blockIdx.y;
    const int b  = bh >> 4, h = bh & 15;
    const int t0 = blockIdx.x * 64;
    const int tid = threadIdx.x;

    {
        const float4* src = (const float4*)(g_rv + (size_t)bh*KK*HDIM);
        float4* dst = (float4*)&srv[0][0];
        dst[tid]       = src[tid];
        dst[tid + 256] = src[tid + 256];
    }
    {
        const float4* src = (const float4*)(basis + ((size_t)b*TT + t0) * KK);
        float4* dst = (float4*)&sbas[0][0];
        dst[tid]       = src[tid];
        dst[tid + 256] = src[tid + 256];
    }
    __syncthreads();

    const int d  = tid & 63;
    const int tr = tid >> 6;   // 0..3
    float acc[16];
#pragma unroll
    for (int i = 0; i < 16; i++) acc[i] = 0.f;
#pragma unroll
    for (int k = 0; k < KK; k++) {
        float rvv = srv[k][d];
#pragma unroll
        for (int i = 0; i < 16; i++)
            acc[i] += sbas[tr + 4*i][k] * rvv;
    }
#pragma unroll
    for (int i = 0; i < 16; i++) {
        int t = t0 + tr + 4*i;
        g_outpre[((size_t)b*TT + t)*DD + h*HDIM + d] = acc[i];
    }
}

// ---------------- launch ----------------
extern "C" void kernel_launch(void* const* d_in, const int* in_sizes, int n_in,
                              void* d_out, int out_size) {
    const float* x     = (const float*)d_in[0];
    const float* basis = (const float*)d_in[1];
    const float* Wqkv  = (const float*)d_in[2];
    const float* Wout  = (const float*)d_in[3];
    const float* pa    = (const float*)d_in[4];
    const float* pb    = (const float*)d_in[5];
    const float* W1    = (const float*)d_in[6];
    const float* b1    = (const float*)d_in[7];
    const float* W2    = (const float*)d_in[8];
    const float* b2    = (const float*)d_in[9];
    const float* sfilt = (const float*)d_in[10];

    float* out      = (float*)d_out;                 // (B,T,D)
    float* out_pw   = out + (size_t)BB*TT*DD;        // (B,H)
    float* out_resp = out_pw + BH;                   // (B,H,K)

    // 1) qkv = x @ W_qkv^T
    gemm1_kernel<<<dim3(D3/128, (BB*TT)/128), 256>>>(x, Wqkv);
    // 2) qm partials + pulse widths
    qmean_part_kernel<<<dim3(BH, 32), 64>>>();
    pulse_kernel<<<BH, 64>>>(W1, b1, W2, b2, out_pw);
    // 3) spectral projections for q,k,v
    spec_kernel<<<dim3(BH, 3), 128>>>(basis);
    // 4) attn_spec + filter + soliton (scalar ODE)
    soliton_kernel<<<BH, 32>>>(sfilt, pa, pb, out_resp);
    // 5) rv = response * v_spec
    rv_kernel<<<512, 256>>>();
    // 6) synthesis back to time domain
    synth_kernel<<<dim3(TT/64, BH), 256>>>(basis);
    // 7) out = outpre @ W_out^T
    gemm2_kernel<<<dim3(DD/128, (BB*TT)/128), 256>>>(Wout, out);
}

// round 3
// speedup vs baseline: 20.4864x; 20.4864x over previous
#include <cuda_runtime.h>
#include <math.h>

// Problem constants
#define BB   4
#define TT   4096
#define DD   1024
#define HH   16
#define HDIM 64
#define KK   32
#define D3   (3*DD)
#define BH   (BB*HH)

#define TSPLIT 16   // T split for xs partials (256 t each)
#define KSPL_B 8    // K split for spec3 GEMM (128 k each)
#define KSPL_D 8    // K split for M GEMM (128 k each)

// ---------------- scratch (device globals; no allocation) ----------------
__device__ float g_xs_part[TSPLIT*BB*KK*DD];   // 2M floats
__device__ float g_xm_part[TSPLIT*BB*DD];      // 64K
__device__ float g_xs[BB*KK*DD];               // 131072  (row = b*32+k)
__device__ float g_xm[BB*DD];                  // mean_t x
__device__ float g_sp_part[KSPL_B*BB*KK*D3];   // 3.1M floats
__device__ float g_spec3[BB*KK*D3];            // 393216 (row b*32+k, col 0..3071)
__device__ float g_resp[BH*KK];
__device__ float g_rv[BB*KK*DD];               // RV: (b*32+k, j)
__device__ float g_M_part[KSPL_D*BB*KK*DD];    // 1M floats
__device__ float g_M[BB*KK*DD];                // (b, k, i)

// =============== 1) xs[b,k,j] = sum_t basis[b,t,k]*x[b,t,j]; xm partials =====
// grid (b=4, jt=8, ts=16), 256 threads
__global__ void __launch_bounds__(256)
xs_kernel(const float* __restrict__ x, const float* __restrict__ basis) {
    __shared__ float xt[32][128];   // 16KB
    __shared__ float bt[32][32];    // 4KB
    const int b  = blockIdx.x;
    const int jt = blockIdx.y;
    const int ts = blockIdx.z;
    const int tid = threadIdx.x;
    const int tx = tid & 31;        // j quad
    const int ky = tid >> 5;        // 0..7 (warp id)
    const int j0 = jt * 128;

    float acc[4][4];
#pragma unroll
    for (int i = 0; i < 4; i++)
#pragma unroll
        for (int j = 0; j < 4; j++) acc[i][j] = 0.f;
    float xs0 = 0.f, xs1 = 0.f, xs2 = 0.f, xs3 = 0.f;

    for (int tc = 0; tc < 8; tc++) {
        const int t0 = ts*256 + tc*32;
#pragma unroll
        for (int i = 0; i < 4; i++) {
            int f = tid + 256*i;               // 0..1023
            int row = f >> 5, c4 = (f & 31) * 4;
            *(float4*)&xt[row][c4] =
                *(const float4*)(x + ((size_t)(b*TT + t0 + row))*DD + j0 + c4);
        }
        ((float4*)&bt[0][0])[tid] = ((const float4*)(basis + ((size_t)(b*TT + t0))*KK))[tid];
        __syncthreads();
#pragma unroll
        for (int t = 0; t < 32; t++) {
            float4 xv = *(const float4*)&xt[t][tx*4];
            float b0 = bt[t][ky],    b1 = bt[t][ky+8];
            float b2 = bt[t][ky+16], b3 = bt[t][ky+24];
            acc[0][0] += b0*xv.x; acc[0][1] += b0*xv.y; acc[0][2] += b0*xv.z; acc[0][3] += b0*xv.w;
            acc[1][0] += b1*xv.x; acc[1][1] += b1*xv.y; acc[1][2] += b1*xv.z; acc[1][3] += b1*xv.w;
            acc[2][0] += b2*xv.x; acc[2][1] += b2*xv.y; acc[2][2] += b2*xv.z; acc[2][3] += b2*xv.w;
            acc[3][0] += b3*xv.x; acc[3][1] += b3*xv.y; acc[3][2] += b3*xv.z; acc[3][3] += b3*xv.w;
            if (ky == 0) { xs0 += xv.x; xs1 += xv.y; xs2 += xv.z; xs3 += xv.w; }
        }
        __syncthreads();
    }
#pragma unroll
    for (int kq = 0; kq < 4; kq++) {
        int k = ky + 8*kq;
        *(float4*)&g_xs_part[(((size_t)ts*BB + b)*KK + k)*DD + j0 + tx*4] =
            make_float4(acc[kq][0], acc[kq][1], acc[kq][2], acc[kq][3]);
    }
    if (ky == 0)
        *(float4*)&g_xm_part[((size_t)ts*BB + b)*DD + j0 + tx*4] =
            make_float4(xs0, xs1, xs2, xs3);
}

// =============== 2) reduce xs partials + xm ===============
__global__ void reduceA_kernel() {
    int gid = blockIdx.x * 256 + threadIdx.x;   // 131072
    float s = 0.f;
#pragma unroll
    for (int ts = 0; ts < TSPLIT; ts++) s += g_xs_part[(size_t)ts*131072 + gid];
    g_xs[gid] = s;
    if (gid < BB*DD) {
        float m = 0.f;
#pragma unroll
        for (int ts = 0; ts < TSPLIT; ts++) m += g_xm_part[(size_t)ts*BB*DD + gid];
        g_xm[gid] = m * (1.0f / (float)TT);
    }
}

// =============== 3) spec3 = xs(128x1024) @ W_qkv^T(3072x1024), split-K =======
// grid (nt=24, ks=8), 256 threads; 128x128 tile, Kchunk=128
__global__ void __launch_bounds__(256)
gemmB_kernel(const float* __restrict__ Wqkv) {
    __shared__ float As[8][128];
    __shared__ float Bs[8][128];
    const int bn = blockIdx.x * 128;
    const int ks = blockIdx.y;
    const int tid = threadIdx.x;
    const int tx = tid & 15, ty = tid >> 4;
    const int lr = tid >> 1, lc = (tid & 1) << 2;

    const float* Ap = g_xs + (size_t)lr*DD + ks*128 + lc;
    const float* Bp = Wqkv + (size_t)(bn + lr)*DD + ks*128 + lc;

    float acc[8][8];
#pragma unroll
    for (int i = 0; i < 8; i++)
#pragma unroll
        for (int j = 0; j < 8; j++) acc[i][j] = 0.f;

    for (int k0 = 0; k0 < 128; k0 += 8) {
        float4 av = *(const float4*)(Ap + k0);
        float4 bv = *(const float4*)(Bp + k0);
        As[lc+0][lr] = av.x; As[lc+1][lr] = av.y; As[lc+2][lr] = av.z; As[lc+3][lr] = av.w;
        Bs[lc+0][lr] = bv.x; Bs[lc+1][lr] = bv.y; Bs[lc+2][lr] = bv.z; Bs[lc+3][lr] = bv.w;
        __syncthreads();
#pragma unroll
        for (int kk = 0; kk < 8; kk++) {
            float ra[8], rb[8];
            *(float4*)(ra)   = *(const float4*)(&As[kk][ty*8]);
            *(float4*)(ra+4) = *(const float4*)(&As[kk][ty*8+4]);
            *(float4*)(rb)   = *(const float4*)(&Bs[kk][tx*8]);
            *(float4*)(rb+4) = *(const float4*)(&Bs[kk][tx*8+4]);
#pragma unroll
            for (int i = 0; i < 8; i++)
#pragma unroll
                for (int j = 0; j < 8; j++)
                    acc[i][j] += ra[i] * rb[j];
        }
        __syncthreads();
    }
#pragma unroll
    for (int i = 0; i < 8; i++) {
        float* Cp = g_sp_part + ((size_t)ks*128 + ty*8 + i)*D3 + bn + tx*8;
        *(float4*)(Cp)   = make_float4(acc[i][0], acc[i][1], acc[i][2], acc[i][3]);
        *(float4*)(Cp+4) = make_float4(acc[i][4], acc[i][5], acc[i][6], acc[i][7]);
    }
}

__global__ void reduceB_kernel() {
    int gid = blockIdx.x * 256 + threadIdx.x;   // 393216
    float s = 0.f;
#pragma unroll
    for (int ks = 0; ks < KSPL_B; ks++) s += g_sp_part[(size_t)ks*BB*KK*D3 + gid];
    g_spec3[gid] = s;
}

// =============== 4) pulse widths ===============
// grid BH, 64 threads. qm[b,h,d] = dot(W_qkv[h*64+d], xm[b])
__global__ void pulse_kernel(const float* __restrict__ Wqkv,
                             const float* __restrict__ W1, const float* __restrict__ b1,
                             const float* __restrict__ W2, const float* __restrict__ b2,
                             float* __restrict__ out_pw) {
    __shared__ float qm[HDIM];
    __shared__ float h1[32];
    const int bh = blockIdx.x;
    const int b = bh >> 4, h = bh & 15;
    const int d = threadIdx.x;
    const float4* wrow = (const float4*)(Wqkv + (size_t)(h*HDIM + d)*DD);
    const float4* xm   = (const float4*)(g_xm + (size_t)b*DD);
    float s = 0.f;
#pragma unroll 4
    for (int j = 0; j < DD/4; j++) {
        float4 w = wrow[j], xv = xm[j];
        s += w.x*xv.x + w.y*xv.y + w.z*xv.z + w.w*xv.w;
    }
    qm[d] = s;
    __syncthreads();
    if (d < 32) {
        float a = b1[d];
#pragma unroll
        for (int j = 0; j < HDIM; j++) a += qm[j] * W1[d*HDIM + j];
        h1[d] = a / (1.f + expf(-a));      // silu
    }
    __syncthreads();
    if (d == 0) {
        float a = b2[0];
#pragma unroll
        for (int j = 0; j < 32; j++) a += h1[j] * W2[j];
        float spl = (a > 20.f) ? a : log1pf(expf(a));  // softplus
        out_pw[bh] = 4.0f + spl;
    }
}

// =============== 5) attn + filter + scalar soliton ODE ===============
__global__ void soliton_kernel(const float* __restrict__ sfilt,
                               const float* __restrict__ pa, const float* __restrict__ pb,
                               float* __restrict__ out_resp) {
    const int bh = blockIdx.x;
    const int b = bh >> 4, h = bh & 15;
    const int k = threadIdx.x;   // 0..31
    const float* row = g_spec3 + (size_t)(b*KK + k)*D3;
    const float4* qsp = (const float4*)(row + h*HDIM);
    const float4* ksp = (const float4*)(row + DD + h*HDIM);
    float dot = 0.f;
#pragma unroll
    for (int d = 0; d < HDIM/4; d++) {
        float4 qv = qsp[d], kv = ksp[d];
        dot += qv.x*kv.x + qv.y*kv.y + qv.z*kv.z + qv.w*kv.w;
    }
    float filt = 1.f / (1.f + expf(-sfilt[h*KK + k]));
    float s = dot * 0.125f * filt;       // / sqrt(64)

    float scale = fmaxf(fabsf(s), 1e-6f);
    float sn = s / scale;
    float I  = (fabsf(s) > 0.5f) ? sn : 0.1f*sn;
    const float a = *pa, bcoef = *pb;
    const float dt = 0.2f;
    float v = 0.f, w = 0.f;
#pragma unroll
    for (int it = 0; it < 5; it++) {
        float dv = v - v*v*v*(1.f/3.f) - w + I;
        float dw = (v + a - bcoef*w) * 10.f;   // / TAU
        v = fminf(fmaxf(v + dt*dv, -3.f), 3.f);
        w = fminf(fmaxf(w + dt*dw, -3.f), 3.f);
    }
    float r = v * scale;
    g_resp[bh*KK + k]   = r;
    out_resp[bh*KK + k] = r;
}

// =============== 6) RV[b*32+k, j] = resp[b, j>>6, k] * v_spec ===============
__global__ void rv_kernel() {
    int i = blockIdx.x * 256 + threadIdx.x;   // 131072
    int row = i >> 10;            // b*32+k
    int j   = i & 1023;
    int b = row >> 5, k = row & 31, h = j >> 6;
    g_rv[i] = g_resp[(b*HH + h)*KK + k] * g_spec3[(size_t)row*D3 + 2*DD + j];
}

// =============== 7) M[b] = RV[b](32x1024) @ W_out^T(1024x1024), split-K ======
// grid (nt=8, ks=8, b=4), 256 threads; 32x128 tile, Kchunk=128
__global__ void __launch_bounds__(256)
gemmD_kernel(const float* __restrict__ Wout) {
    __shared__ float As[8][32];
    __shared__ float Bs[8][128];
    const int bn = blockIdx.x * 128;
    const int ks = blockIdx.y;
    const int b  = blockIdx.z;
    const int tid = threadIdx.x;
    const int tx = tid & 31;      // n quad
    const int my = tid >> 5;      // 0..7
    const int lr = tid >> 1, lc = (tid & 1) << 2;

    const float* Arow = g_rv + (size_t)b*KK*DD + ks*128;
    const float* Bp   = Wout + (size_t)(bn + lr)*DD + ks*128 + lc;

    float acc[4][4];
#pragma unroll
    for (int i = 0; i < 4; i++)
#pragma unroll
        for (int j = 0; j < 4; j++) acc[i][j] = 0.f;

    for (int k0 = 0; k0 < 128; k0 += 8) {
        if (tid < 64) {
            int ar = tid >> 1, ac = (tid & 1) << 2;
            float4 av = *(const float4*)(Arow + (size_t)ar*DD + k0 + ac);
            As[ac+0][ar] = av.x; As[ac+1][ar] = av.y; As[ac+2][ar] = av.z; As[ac+3][ar] = av.w;
        }
        float4 bv = *(const float4*)(Bp + k0);
        Bs[lc+0][lr] = bv.x; Bs[lc+1][lr] = bv.y; Bs[lc+2][lr] = bv.z; Bs[lc+3][lr] = bv.w;
        __syncthreads();
#pragma unroll
        for (int kk = 0; kk < 8; kk++) {
            float ra0 = As[kk][my], ra1 = As[kk][my+8], ra2 = As[kk][my+16], ra3 = As[kk][my+24];
            float4 rb = *(const float4*)(&Bs[kk][tx*4]);
            acc[0][0] += ra0*rb.x; acc[0][1] += ra0*rb.y; acc[0][2] += ra0*rb.z; acc[0][3] += ra0*rb.w;
            acc[1][0] += ra1*rb.x; acc[1][1] += ra1*rb.y; acc[1][2] += ra1*rb.z; acc[1][3] += ra1*rb.w;
            acc[2][0] += ra2*rb.x; acc[2][1] += ra2*rb.y; acc[2][2] += ra2*rb.z; acc[2][3] += ra2*rb.w;
            acc[3][0] += ra3*rb.x; acc[3][1] += ra3*rb.y; acc[3][2] += ra3*rb.z; acc[3][3] += ra3*rb.w;
        }
        __syncthreads();
    }
#pragma unroll
    for (int mi = 0; mi < 4; mi++) {
        int m = my + 8*mi;
        *(float4*)&g_M_part[(((size_t)ks*BB + b)*KK + m)*DD + bn + tx*4] =
            make_float4(acc[mi][0], acc[mi][1], acc[mi][2], acc[mi][3]);
    }
}

__global__ void reduceD_kernel() {
    int gid = blockIdx.x * 256 + threadIdx.x;   // 131072
    float s = 0.f;
#pragma unroll
    for (int ks = 0; ks < KSPL_D; ks++) s += g_M_part[(size_t)ks*131072 + gid];
    g_M[gid] = s;
}

// =============== 8) out[b,t,i] = sum_k basis[b,t,k] * M[b,k,i] ===============
// grid (jt=4, tt=64, b=4), 256 threads; 64t x 256j tile
__global__ void __launch_bounds__(256)
out_kernel(const float* __restrict__ basis, float* __restrict__ out) {
    __shared__ float Ms[KK][256];   // 32KB
    __shared__ float bs[64][KK];    // 8KB
    const int jt = blockIdx.x, tt = blockIdx.y, b = blockIdx.z;
    const int t0 = tt*64, j0 = jt*256;
    const int tid = threadIdx.x;

#pragma unroll
    for (int i = 0; i < 8; i++) {
        int f = tid + 256*i;        // 0..2047
        int row = f >> 6, c4 = (f & 63) * 4;
        *(float4*)&Ms[row][c4] = *(const float4*)(g_M + ((size_t)b*KK + row)*DD + j0 + c4);
    }
#pragma unroll
    for (int i = 0; i < 2; i++) {
        int f = tid + 256*i;        // 0..511
        ((float4*)&bs[0][0])[f] = ((const float4*)(basis + ((size_t)b*TT + t0)*KK))[f];
    }
    __syncthreads();

    const int jx = tid & 63;        // j quad
    const int ty = tid >> 6;        // 0..3
    float4 acc[16];
#pragma unroll
    for (int i = 0; i < 16; i++) acc[i] = make_float4(0.f, 0.f, 0.f, 0.f);
#pragma unroll
    for (int k = 0; k < KK; k++) {
        float4 mv = *(const float4*)&Ms[k][jx*4];
#pragma unroll
        for (int i = 0; i < 16; i++) {
            float bb = bs[ty + 4*i][k];
            acc[i].x += bb*mv.x; acc[i].y += bb*mv.y; acc[i].z += bb*mv.z; acc[i].w += bb*mv.w;
        }
    }
#pragma unroll
    for (int i = 0; i < 16; i++) {
        int t = t0 + ty + 4*i;
        *(float4*)(out + ((size_t)b*TT + t)*DD + j0 + jx*4) = acc[i];
    }
}

// ---------------- launch ----------------
extern "C" void kernel_launch(void* const* d_in, const int* in_sizes, int n_in,
                              void* d_out, int out_size) {
    const float* x     = (const float*)d_in[0];
    const float* basis = (const float*)d_in[1];
    const float* Wqkv  = (const float*)d_in[2];
    const float* Wout  = (const float*)d_in[3];
    const float* pa    = (const float*)d_in[4];
    const float* pb    = (const float*)d_in[5];
    const float* W1    = (const float*)d_in[6];
    const float* b1    = (const float*)d_in[7];
    const float* W2    = (const float*)d_in[8];
    const float* b2    = (const float*)d_in[9];
    const float* sfilt = (const float*)d_in[10];

    float* out      = (float*)d_out;                 // (B,T,D)
    float* out_pw   = out + (size_t)BB*TT*DD;        // (B,H)
    float* out_resp = out_pw + BH;                   // (B,H,K)

    // 1) xs = basis^T x (+ xm partials)
    xs_kernel<<<dim3(BB, 8, TSPLIT), 256>>>(x, basis);
    reduceA_kernel<<<512, 256>>>();
    // 2) spec3 = xs @ W_qkv^T  (holds q_spec | k_spec | v_spec)
    gemmB_kernel<<<dim3(24, KSPL_B), 256>>>(Wqkv);
    reduceB_kernel<<<1536, 256>>>();
    // 3) pulse widths from xm
    pulse_kernel<<<BH, 64>>>(Wqkv, W1, b1, W2, b2, out_pw);
    // 4) attn + soliton (scalar ODE per (b,h,k))
    soliton_kernel<<<BH, 32>>>(sfilt, pa, pb, out_resp);
    // 5) RV = response * v_spec
    rv_kernel<<<512, 256>>>();
    // 6) M = RV @ W_out^T
    gemmD_kernel<<<dim3(8, KSPL_D, BB), 256>>>(Wout);
    reduceD_kernel<<<512, 256>>>();
    // 7) out = basis @ M
    out_kernel<<<dim3(4, 64, BB), 256>>>(basis, out);
}

// round 6
// speedup vs baseline: 22.5867x; 1.1025x over previous
#include <cuda_runtime.h>
#include <math.h>

// Problem constants
#define BB   4
#define TT   4096
#define DD   1024
#define HH   16
#define HDIM 64
#define KK   32
#define D3   (3*DD)
#define BH   (BB*HH)

#define TSPLIT 16   // T split for xs partials (256 t each)
#define KSPL_B 8    // K split for spec3 GEMM (128 k each)
#define KSPL_D 8    // K split for M GEMM (128 k each)

typedef unsigned long long ull;

// ---- packed f32x2 helpers (FFMA2: 2x fp32 throughput on sm_103a) ----
__device__ __forceinline__ ull pk2(float lo, float hi) {
    ull r; asm("mov.b64 %0, {%1,%2};" : "=l"(r) : "f"(lo), "f"(hi)); return r;
}
__device__ __forceinline__ void ffma2(ull& d, ull a, ull b) {
    asm("fma.rn.f32x2 %0, %1, %2, %3;" : "=l"(d) : "l"(a), "l"(b), "l"(d));
}
__device__ __forceinline__ float2 up2(ull v) {
    float2 r; asm("mov.b64 {%0,%1}, %2;" : "=f"(r.x), "=f"(r.y) : "l"(v)); return r;
}

// ---------------- scratch (device globals; no allocation) ----------------
__device__ float g_xs_part[TSPLIT*BB*KK*DD];   // 8MB
__device__ float g_xm_part[TSPLIT*BB*DD];
__device__ float g_xs[BB*KK*DD];               // (b*32+k, j)
__device__ float g_xm[BB*DD];
__device__ float g_sp_part[KSPL_B*BB*KK*D3];
__device__ float g_spec3[BB*KK*D3];            // (b*32+k, 0..3071)
__device__ float g_resp[BH*KK];
__device__ float g_M_part[KSPL_D*BB*KK*DD];
__device__ float g_M[BB*KK*DD];                // (b, k, i)

// =============== 1) xs[b,k,j] = sum_t basis[b,t,k]*x[b,t,j] (+xm partials) ===
// grid (b=4, jt=4, ts=16), 128 threads. j-tile 256, per-thread 8k x 8j.
__global__ void __launch_bounds__(128)
xs_kernel(const float* __restrict__ x, const float* __restrict__ basis) {
    __shared__ float xt[32][256];   // 32KB
    __shared__ float bt[32][32];    // 4KB
    const int b  = blockIdx.x;
    const int jt = blockIdx.y;
    const int ts = blockIdx.z;
    const int tid = threadIdx.x;
    const int jx = tid & 31;        // j lane: cols jx*4..+3 and 128+jx*4..+3
    const int ky = tid >> 5;        // 0..3 ; k = ky + 4*kq
    const int j0 = jt * 256;

    ull acc2[8][4];                 // [kq][jpair]
#pragma unroll
    for (int i = 0; i < 8; i++)
#pragma unroll
        for (int j = 0; j < 4; j++) acc2[i][j] = 0ull;
    ull accm[4] = {0ull, 0ull, 0ull, 0ull};
    const ull kONE = pk2(1.f, 1.f);

    for (int tc = 0; tc < 8; tc++) {
        const int t0 = ts*256 + tc*32;
        // stage x tile: 32 t x 256 j
#pragma unroll
        for (int i = 0; i < 16; i++) {
            int f = tid + 128*i;            // 0..2047 float4 slots
            int row = f >> 6, c4 = (f & 63) * 4;
            *(float4*)&xt[row][c4] =
                *(const float4*)(x + ((size_t)(b*TT + t0 + row))*DD + j0 + c4);
        }
        // stage basis tile: 32 t x 32 k
        ((float4*)&bt[0][0])[tid]       = ((const float4*)(basis + ((size_t)(b*TT + t0))*KK))[tid];
        ((float4*)&bt[0][0])[tid + 128] = ((const float4*)(basis + ((size_t)(b*TT + t0))*KK))[tid + 128];
        __syncthreads();
#pragma unroll
        for (int t = 0; t < 32; t++) {
            ulonglong2 xa = *(const ulonglong2*)&xt[t][jx*4];
            ulonglong2 xb = *(const ulonglong2*)&xt[t][jx*4 + 128];
#pragma unroll
            for (int kq = 0; kq < 8; kq++) {
                float bv = bt[t][ky + 4*kq];
                ull bp = pk2(bv, bv);
                ffma2(acc2[kq][0], bp, xa.x);
                ffma2(acc2[kq][1], bp, xa.y);
                ffma2(acc2[kq][2], bp, xb.x);
                ffma2(acc2[kq][3], bp, xb.y);
            }
            if (ky == 0) {
                ffma2(accm[0], xa.x, kONE);
                ffma2(accm[1], xa.y, kONE);
                ffma2(accm[2], xb.x, kONE);
                ffma2(accm[3], xb.y, kONE);
            }
        }
        __syncthreads();
    }
#pragma unroll
    for (int kq = 0; kq < 8; kq++) {
        int k = ky + 4*kq;
        size_t base = (((size_t)ts*BB + b)*KK + k)*DD + j0;
        *(ulonglong2*)&g_xs_part[base + jx*4]       = make_ulonglong2(acc2[kq][0], acc2[kq][1]);
        *(ulonglong2*)&g_xs_part[base + jx*4 + 128] = make_ulonglong2(acc2[kq][2], acc2[kq][3]);
    }
    if (ky == 0) {
        size_t base = ((size_t)ts*BB + b)*DD + j0;
        *(ulonglong2*)&g_xm_part[base + jx*4]       = make_ulonglong2(accm[0], accm[1]);
        *(ulonglong2*)&g_xm_part[base + jx*4 + 128] = make_ulonglong2(accm[2], accm[3]);
    }
}

// =============== 2) reduce xs partials + xm ===============
__global__ void reduceA_kernel() {
    int gid = blockIdx.x * 256 + threadIdx.x;   // 131072
    float s = 0.f;
#pragma unroll
    for (int ts = 0; ts < TSPLIT; ts++) s += g_xs_part[(size_t)ts*131072 + gid];
    g_xs[gid] = s;
    if (gid < BB*DD) {
        float m = 0.f;
#pragma unroll
        for (int ts = 0; ts < TSPLIT; ts++) m += g_xm_part[(size_t)ts*BB*DD + gid];
        g_xm[gid] = m * (1.0f / (float)TT);
    }
}

// =============== 3) spec3 = xs(128x1024) @ Wqkv^T(3072x1024), split-K =======
// grid (nt=48, ks=8), 256 threads; 128x64 tile, Kchunk=128, per-thread 8m x 4n.
__global__ void __launch_bounds__(256)
gemmB_kernel(const float* __restrict__ Wqkv) {
    __shared__ float As[8][128];
    __shared__ float Bs[8][64];
    const int bn = blockIdx.x * 64;
    const int ks = blockIdx.y;
    const int tid = threadIdx.x;
    const int tx = tid & 15;        // n: tx*4..+3
    const int ty = tid >> 4;        // m: ty*8..+7
    const int lr = tid >> 1, lc = (tid & 1) << 2;
    const int br = tid >> 2, bc = (tid & 3) << 1;

    const float* Ap = g_xs + (size_t)lr*DD + ks*128 + lc;
    const float* Bp = Wqkv + (size_t)(bn + br)*DD + ks*128 + bc;

    ull acc2[4][4];                 // [mpair][n]
#pragma unroll
    for (int i = 0; i < 4; i++)
#pragma unroll
        for (int j = 0; j < 4; j++) acc2[i][j] = 0ull;

    for (int k0 = 0; k0 < 128; k0 += 8) {
        float4 av = *(const float4*)(Ap + k0);
        As[lc+0][lr] = av.x; As[lc+1][lr] = av.y; As[lc+2][lr] = av.z; As[lc+3][lr] = av.w;
        float2 bv = *(const float2*)(Bp + k0);
        Bs[bc][br] = bv.x; Bs[bc+1][br] = bv.y;
        __syncthreads();
#pragma unroll
        for (int kk = 0; kk < 8; kk++) {
            ulonglong2 aa = *(const ulonglong2*)&As[kk][ty*8];      // m pairs (0,1),(2,3)
            ulonglong2 ab = *(const ulonglong2*)&As[kk][ty*8 + 4];  // (4,5),(6,7)
            float4 rb = *(const float4*)&Bs[kk][tx*4];
            ull b0 = pk2(rb.x, rb.x), b1 = pk2(rb.y, rb.y);
            ull b2 = pk2(rb.z, rb.z), b3 = pk2(rb.w, rb.w);
            ffma2(acc2[0][0], aa.x, b0); ffma2(acc2[0][1], aa.x, b1);
            ffma2(acc2[0][2], aa.x, b2); ffma2(acc2[0][3], aa.x, b3);
            ffma2(acc2[1][0], aa.y, b0); ffma2(acc2[1][1], aa.y, b1);
            ffma2(acc2[1][2], aa.y, b2); ffma2(acc2[1][3], aa.y, b3);
            ffma2(acc2[2][0], ab.x, b0); ffma2(acc2[2][1], ab.x, b1);
            ffma2(acc2[2][2], ab.x, b2); ffma2(acc2[2][3], ab.x, b3);
            ffma2(acc2[3][0], ab.y, b0); ffma2(acc2[3][1], ab.y, b1);
            ffma2(acc2[3][2], ab.y, b2); ffma2(acc2[3][3], ab.y, b3);
        }
        __syncthreads();
    }
#pragma unroll
    for (int p = 0; p < 4; p++) {
        float2 v0 = up2(acc2[p][0]), v1 = up2(acc2[p][1]);
        float2 v2 = up2(acc2[p][2]), v3 = up2(acc2[p][3]);
        int m = ty*8 + 2*p;
        *(float4*)&g_sp_part[((size_t)ks*128 + m  )*D3 + bn + tx*4] = make_float4(v0.x, v1.x, v2.x, v3.x);
        *(float4*)&g_sp_part[((size_t)ks*128 + m+1)*D3 + bn + tx*4] = make_float4(v0.y, v1.y, v2.y, v3.y);
    }
}

__global__ void reduceB_kernel() {
    int gid = blockIdx.x * 256 + threadIdx.x;   // 393216
    float s = 0.f;
#pragma unroll
    for (int ks = 0; ks < KSPL_B; ks++) s += g_sp_part[(size_t)ks*BB*KK*D3 + gid];
    g_spec3[gid] = s;
}

// =============== 4) pulse widths ===============
__global__ void pulse_kernel(const float* __restrict__ Wqkv,
                             const float* __restrict__ W1, const float* __restrict__ b1,
                             const float* __restrict__ W2, const float* __restrict__ b2,
                             float* __restrict__ out_pw) {
    __shared__ float qm[HDIM];
    __shared__ float h1[32];
    const int bh = blockIdx.x;
    const int b = bh >> 4, h = bh & 15;
    const int d = threadIdx.x;
    const float4* wrow = (const float4*)(Wqkv + (size_t)(h*HDIM + d)*DD);
    const float4* xm   = (const float4*)(g_xm + (size_t)b*DD);
    float s = 0.f;
#pragma unroll 4
    for (int j = 0; j < DD/4; j++) {
        float4 w = wrow[j], xv = xm[j];
        s += w.x*xv.x + w.y*xv.y + w.z*xv.z + w.w*xv.w;
    }
    qm[d] = s;
    __syncthreads();
    if (d < 32) {
        float a = b1[d];
#pragma unroll
        for (int j = 0; j < HDIM; j++) a += qm[j] * W1[d*HDIM + j];
        h1[d] = a / (1.f + expf(-a));      // silu
    }
    __syncthreads();
    if (d == 0) {
        float a = b2[0];
#pragma unroll
        for (int j = 0; j < 32; j++) a += h1[j] * W2[j];
        float spl = (a > 20.f) ? a : log1pf(expf(a));  // softplus
        out_pw[bh] = 4.0f + spl;
    }
}

// =============== 5) attn + filter + scalar soliton ODE ===============
__global__ void soliton_kernel(const float* __restrict__ sfilt,
                               const float* __restrict__ pa, const float* __restrict__ pb,
                               float* __restrict__ out_resp) {
    const int bh = blockIdx.x;
    const int b = bh >> 4, h = bh & 15;
    const int k = threadIdx.x;   // 0..31
    const float* row = g_spec3 + (size_t)(b*KK + k)*D3;
    const float4* qsp = (const float4*)(row + h*HDIM);
    const float4* ksp = (const float4*)(row + DD + h*HDIM);
    float dot = 0.f;
#pragma unroll
    for (int d = 0; d < HDIM/4; d++) {
        float4 qv = qsp[d], kv = ksp[d];
        dot += qv.x*kv.x + qv.y*kv.y + qv.z*kv.z + qv.w*kv.w;
    }
    float filt = 1.f / (1.f + expf(-sfilt[h*KK + k]));
    float s = dot * 0.125f * filt;       // / sqrt(64)

    float scale = fmaxf(fabsf(s), 1e-6f);
    float sn = s / scale;
    float I  = (fabsf(s) > 0.5f) ? sn : 0.1f*sn;
    const float a = *pa, bcoef = *pb;
    const float dt = 0.2f;
    float v = 0.f, w = 0.f;
#pragma unroll
    for (int it = 0; it < 5; it++) {
        float dv = v - v*v*v*(1.f/3.f) - w + I;
        float dw = (v + a - bcoef*w) * 10.f;   // / TAU
        v = fminf(fmaxf(v + dt*dv, -3.f), 3.f);
        w = fminf(fmaxf(w + dt*dw, -3.f), 3.f);
    }
    float r = v * scale;
    g_resp[bh*KK + k]   = r;
    out_resp[bh*KK + k] = r;
}

// =============== 6) M[b] = (resp*v_spec)(32x1024) @ Wout^T, split-K ==========
// rv fused into the A-tile load. grid (nt=8, ks=8, b=4), 256 threads.
__global__ void __launch_bounds__(256)
gemmD_kernel(const float* __restrict__ Wout) {
    __shared__ float As[8][32];
    __shared__ float Bs[8][128];
    const int bn = blockIdx.x * 128;
    const int ks = blockIdx.y;
    const int b  = blockIdx.z;
    const int tid = threadIdx.x;
    const int tx = tid & 31;      // n: tx*4..+3
    const int my = tid >> 5;      // m: my + 8*mi
    const int lr = tid >> 1, lc = (tid & 1) << 2;

    const float* Bp = Wout + (size_t)(bn + lr)*DD + ks*128 + lc;

    ull acc2[4][2];
#pragma unroll
    for (int i = 0; i < 4; i++) { acc2[i][0] = 0ull; acc2[i][1] = 0ull; }

    for (int k0 = 0; k0 < 128; k0 += 8) {
        if (tid < 64) {
            int ar = tid >> 1, ac = (tid & 1) << 2;
            int col = ks*128 + k0 + ac;
            float4 av = *(const float4*)(g_spec3 + ((size_t)(b*KK + ar))*D3 + 2*DD + col);
            float r = g_resp[(b*HH + (col >> 6))*KK + ar];   // rv fusion
            As[ac+0][ar] = av.x * r; As[ac+1][ar] = av.y * r;
            As[ac+2][ar] = av.z * r; As[ac+3][ar] = av.w * r;
        }
        float4 bv = *(const float4*)(Bp + k0);
        Bs[lc+0][lr] = bv.x; Bs[lc+1][lr] = bv.y; Bs[lc+2][lr] = bv.z; Bs[lc+3][lr] = bv.w;
        __syncthreads();
#pragma unroll
        for (int kk = 0; kk < 8; kk++) {
            ulonglong2 rb = *(const ulonglong2*)&Bs[kk][tx*4];
            float a0 = As[kk][my], a1 = As[kk][my+8], a2 = As[kk][my+16], a3 = As[kk][my+24];
            ull p0 = pk2(a0,a0), p1 = pk2(a1,a1), p2 = pk2(a2,a2), p3 = pk2(a3,a3);
            ffma2(acc2[0][0], p0, rb.x); ffma2(acc2[0][1], p0, rb.y);
            ffma2(acc2[1][0], p1, rb.x); ffma2(acc2[1][1], p1, rb.y);
            ffma2(acc2[2][0], p2, rb.x); ffma2(acc2[2][1], p2, rb.y);
            ffma2(acc2[3][0], p3, rb.x); ffma2(acc2[3][1], p3, rb.y);
        }
        __syncthreads();
    }
#pragma unroll
    for (int mi = 0; mi < 4; mi++) {
        int m = my + 8*mi;
        *(ulonglong2*)&g_M_part[(((size_t)ks*BB + b)*KK + m)*DD + bn + tx*4] =
            make_ulonglong2(acc2[mi][0], acc2[mi][1]);
    }
}

__global__ void reduceD_kernel() {
    int gid = blockIdx.x * 256 + threadIdx.x;   // 131072
    float s = 0.f;
#pragma unroll
    for (int ks = 0; ks < KSPL_D; ks++) s += g_M_part[(size_t)ks*131072 + gid];
    g_M[gid] = s;
}

// =============== 7) out[b,t,i] = sum_k basis[b,t,k] * M[b,k,i] ===============
// grid (jt=4, tt=64, b=4), 256 threads; 64t x 256j tile, per-thread 8t x 8j.
__global__ void __launch_bounds__(256)
out_kernel(const float* __restrict__ basis, float* __restrict__ out) {
    __shared__ float Ms[KK][256];   // 32KB
    __shared__ float bs[64][KK];    // 8KB
    const int jt = blockIdx.x, tt = blockIdx.y, b = blockIdx.z;
    const int t0 = tt*64, j0 = jt*256;
    const int tid = threadIdx.x;
    const int jx = tid & 31;        // j: jx*4..+3 and 128+jx*4..+3
    const int ty = tid >> 5;        // t: ty*8..+7

#pragma unroll
    for (int i = 0; i < 8; i++) {
        int f = tid + 256*i;        // 0..2047
        int row = f >> 6, c4 = (f & 63) * 4;
        *(float4*)&Ms[row][c4] = *(const float4*)(g_M + ((size_t)b*KK + row)*DD + j0 + c4);
    }
#pragma unroll
    for (int i = 0; i < 2; i++) {
        int f = tid + 256*i;        // 0..511
        ((float4*)&bs[0][0])[f] = ((const float4*)(basis + ((size_t)b*TT + t0)*KK))[f];
    }
    __syncthreads();

    ull acc2[8][4];                 // [t][jpair]
#pragma unroll
    for (int i = 0; i < 8; i++)
#pragma unroll
        for (int j = 0; j < 4; j++) acc2[i][j] = 0ull;

#pragma unroll
    for (int k = 0; k < KK; k++) {
        ulonglong2 ma = *(const ulonglong2*)&Ms[k][jx*4];
        ulonglong2 mb = *(const ulonglong2*)&Ms[k][jx*4 + 128];
#pragma unroll
        for (int i = 0; i < 8; i++) {
            float bb = bs[ty*8 + i][k];
            ull bp = pk2(bb, bb);
            ffma2(acc2[i][0], bp, ma.x);
            ffma2(acc2[i][1], bp, ma.y);
            ffma2(acc2[i][2], bp, mb.x);
            ffma2(acc2[i][3], bp, mb.y);
        }
    }
#pragma unroll
    for (int i = 0; i < 8; i++) {
        int t = t0 + ty*8 + i;
        size_t base = ((size_t)b*TT + t)*DD + j0;
        *(ulonglong2*)(out + base + jx*4)       = make_ulonglong2(acc2[i][0], acc2[i][1]);
        *(ulonglong2*)(out + base + jx*4 + 128) = make_ulonglong2(acc2[i][2], acc2[i][3]);
    }
}

// ---------------- launch ----------------
extern "C" void kernel_launch(void* const* d_in, const int* in_sizes, int n_in,
                              void* d_out, int out_size) {
    const float* x     = (const float*)d_in[0];
    const float* basis = (const float*)d_in[1];
    const float* Wqkv  = (const float*)d_in[2];
    const float* Wout  = (const float*)d_in[3];
    const float* pa    = (const float*)d_in[4];
    const float* pb    = (const float*)d_in[5];
    const float* W1    = (const float*)d_in[6];
    const float* b1    = (const float*)d_in[7];
    const float* W2    = (const float*)d_in[8];
    const float* b2    = (const float*)d_in[9];
    const float* sfilt = (const float*)d_in[10];

    float* out      = (float*)d_out;                 // (B,T,D)
    float* out_pw   = out + (size_t)BB*TT*DD;        // (B,H)
    float* out_resp = out_pw + BH;                   // (B,H,K)

    xs_kernel<<<dim3(BB, 4, TSPLIT), 128>>>(x, basis);
    reduceA_kernel<<<512, 256>>>();
    gemmB_kernel<<<dim3(48, KSPL_B), 256>>>(Wqkv);
    reduceB_kernel<<<1536, 256>>>();
    pulse_kernel<<<BH, 64>>>(Wqkv, W1, b1, W2, b2, out_pw);
    soliton_kernel<<<BH, 32>>>(sfilt, pa, pb, out_resp);
    gemmD_kernel<<<dim3(8, KSPL_D, BB), 256>>>(Wout);
    reduceD_kernel<<<512, 256>>>();
    out_kernel<<<dim3(4, 64, BB), 256>>>(basis, out);
}

// round 8
// speedup vs baseline: 25.4050x; 1.1248x over previous
#include <cuda_runtime.h>
#include <math.h>
#include <stdint.h>

// Problem constants
#define BB   4
#define TT   4096
#define DD   1024
#define HH   16
#define HDIM 64
#define KK   32
#define D3   (3*DD)
#define BH   (BB*HH)

#define TSPLIT 16   // T split for xs partials (256 t each)
#define KSPL_B 8    // K split for spec3 GEMM (128 k each)
#define KSPL_D 8    // K split for M GEMM (128 k each)

typedef unsigned long long ull;

// ---- packed f32x2 helpers (FFMA2) ----
__device__ __forceinline__ ull pk2(float lo, float hi) {
    ull r; asm("mov.b64 %0, {%1,%2};" : "=l"(r) : "f"(lo), "f"(hi)); return r;
}
__device__ __forceinline__ void ffma2(ull& d, ull a, ull b) {
    asm("fma.rn.f32x2 %0, %1, %2, %3;" : "=l"(d) : "l"(a), "l"(b), "l"(d));
}

// ---- tf32 helpers ----
__device__ __forceinline__ float tf32_rna(float f) {
    unsigned u; asm("cvt.rna.tf32.f32 %0, %1;" : "=r"(u) : "f"(f));
    return __uint_as_float(u);
}
// D += A(16x8) * B(8x8), tf32 inputs (bit patterns in fp32 regs), fp32 accum
__device__ __forceinline__ void mma_tf32(float* c, const float* a, float b0, float b1) {
    asm volatile(
        "mma.sync.aligned.m16n8k8.row.col.f32.tf32.tf32.f32 "
        "{%0,%1,%2,%3},{%4,%5,%6,%7},{%8,%9},{%0,%1,%2,%3};"
        : "+f"(c[0]), "+f"(c[1]), "+f"(c[2]), "+f"(c[3])
        : "r"(__float_as_uint(a[0])), "r"(__float_as_uint(a[1])),
          "r"(__float_as_uint(a[2])), "r"(__float_as_uint(a[3])),
          "r"(__float_as_uint(b0)),  "r"(__float_as_uint(b1)));
}

// ---------------- scratch (device globals; no allocation) ----------------
__device__ float g_xs_part[TSPLIT*BB*KK*DD];   // 8MB
__device__ float g_xm_part[TSPLIT*BB*DD];
__device__ float g_xs[BB*KK*DD];               // (b*32+k, j)
__device__ float g_xm[BB*DD];
__device__ float g_sp_part[KSPL_B*BB*KK*D3];
__device__ float g_spec3[BB*KK*D3];            // (b*32+k, 0..3071)
__device__ float g_resp[BH*KK];
__device__ float g_M_part[KSPL_D*BB*KK*DD];
__device__ float g_M[BB*KK*DD];                // (b, k, i)

// =============== 1) xs[b,k,j] = sum_t basis[b,t,k]*x[b,t,j] (+xm partials) ===
// Tensor-core version. grid (b=4, jt=4, ts=16), 256 threads (8 warps).
// Block: C[32k x 256j] over 256 t. Warp w owns j columns [w*32, w*32+32).
__global__ void __launch_bounds__(256)
xs_kernel(const float* __restrict__ x, const float* __restrict__ basis) {
    __shared__ float xt[32][264];    // x tile, pad 264 (264%32==8)
    __shared__ float bsh[32][40];    // basis hi, pad 40 (40%32==8)
    __shared__ float bsl[32][40];    // basis lo
    __shared__ float xmred[4][256];
    const int b  = blockIdx.x;
    const int jt = blockIdx.y;
    const int ts = blockIdx.z;
    const int tid  = threadIdx.x;
    const int w    = tid >> 5;
    const int lane = tid & 31;
    const int g    = lane >> 2;      // 0..7
    const int tg   = lane & 3;       // 0..3
    const int j0   = jt * 256;

    float c[2][4][4];                // [mtile][ntile][reg]
#pragma unroll
    for (int i = 0; i < 2; i++)
#pragma unroll
        for (int j = 0; j < 4; j++)
#pragma unroll
            for (int r = 0; r < 4; r++) c[i][j][r] = 0.f;
    float4 xmacc = make_float4(0.f, 0.f, 0.f, 0.f);

    for (int tc = 0; tc < 8; tc++) {
        const int t0 = ts*256 + tc*32;
        // stage x tile 32t x 256j (and accumulate column sums for xm)
#pragma unroll
        for (int i = 0; i < 8; i++) {
            int f = tid + 256*i;                 // 0..2047
            int row = f >> 6, c4 = (f & 63) * 4;
            float4 v = *(const float4*)(x + ((size_t)(b*TT + t0 + row))*DD + j0 + c4);
            *(float4*)&xt[row][c4] = v;
            xmacc.x += v.x; xmacc.y += v.y; xmacc.z += v.z; xmacc.w += v.w;
        }
        // stage basis tile 32t x 32k, split hi/lo
        {
            int row = tid >> 3, c4 = (tid & 7) * 4;
            float4 v = *(const float4*)(basis + ((size_t)(b*TT + t0 + row))*KK + c4);
            float hx = tf32_rna(v.x), hy = tf32_rna(v.y), hz = tf32_rna(v.z), hw = tf32_rna(v.w);
            bsh[row][c4+0] = hx; bsh[row][c4+1] = hy; bsh[row][c4+2] = hz; bsh[row][c4+3] = hw;
            bsl[row][c4+0] = v.x - hx; bsl[row][c4+1] = v.y - hy;
            bsl[row][c4+2] = v.z - hz; bsl[row][c4+3] = v.w - hw;
        }
        __syncthreads();
#pragma unroll
        for (int s = 0; s < 4; s++) {
            const int r0 = s*8 + tg, r1 = s*8 + tg + 4;
            float ah[2][4], al[2][4];
#pragma unroll
            for (int mt = 0; mt < 2; mt++) {
                int mb = mt*16;
                ah[mt][0] = bsh[r0][mb+g]; ah[mt][1] = bsh[r0][mb+g+8];
                ah[mt][2] = bsh[r1][mb+g]; ah[mt][3] = bsh[r1][mb+g+8];
                al[mt][0] = bsl[r0][mb+g]; al[mt][1] = bsl[r0][mb+g+8];
                al[mt][2] = bsl[r1][mb+g]; al[mt][3] = bsl[r1][mb+g+8];
            }
#pragma unroll
            for (int nt = 0; nt < 4; nt++) {
                int jl = w*32 + nt*8 + g;
                float b0f = xt[r0][jl];
                float b1f = xt[r1][jl];
                float b0h = tf32_rna(b0f), b1h = tf32_rna(b1f);
                float b0l = b0f - b0h,    b1l = b1f - b1h;
#pragma unroll
                for (int mt = 0; mt < 2; mt++) {
                    mma_tf32(c[mt][nt], ah[mt], b0h, b1h);
                    mma_tf32(c[mt][nt], ah[mt], b0l, b1l);
                    mma_tf32(c[mt][nt], al[mt], b0h, b1h);
                }
            }
        }
        __syncthreads();
    }
    // store C -> g_xs_part
#pragma unroll
    for (int mt = 0; mt < 2; mt++)
#pragma unroll
        for (int nt = 0; nt < 4; nt++) {
            int krow = mt*16 + g;
            int jc = j0 + w*32 + nt*8 + 2*tg;
            size_t base = (((size_t)ts*BB + b)*KK + krow)*DD + jc;
            *(float2*)&g_xs_part[base]          = make_float2(c[mt][nt][0], c[mt][nt][1]);
            *(float2*)&g_xs_part[base + 8*DD]   = make_float2(c[mt][nt][2], c[mt][nt][3]);
        }
    // xm partial reduction
    *(float4*)&xmred[tid >> 6][(tid & 63) * 4] = xmacc;
    __syncthreads();
    if (tid < 64) {
        float4 s = make_float4(0.f, 0.f, 0.f, 0.f);
#pragma unroll
        for (int r = 0; r < 4; r++) {
            float4 v = *(const float4*)&xmred[r][tid*4];
            s.x += v.x; s.y += v.y; s.z += v.z; s.w += v.w;
        }
        *(float4*)&g_xm_part[((size_t)ts*BB + b)*DD + j0 + tid*4] = s;
    }
}

// =============== 2) reduce xs partials + xm ===============
__global__ void reduceA_kernel() {
    int gid = blockIdx.x * 256 + threadIdx.x;   // 131072
    float s = 0.f;
#pragma unroll
    for (int ts = 0; ts < TSPLIT; ts++) s += g_xs_part[(size_t)ts*131072 + gid];
    g_xs[gid] = s;
    if (gid < BB*DD) {
        float m = 0.f;
#pragma unroll
        for (int ts = 0; ts < TSPLIT; ts++) m += g_xm_part[(size_t)ts*BB*DD + gid];
        g_xm[gid] = m * (1.0f / (float)TT);
    }
}

// =============== 3) spec3 = xs(128x1024) @ Wqkv^T(3072x1024), split-K, tensor
// grid (nt=96, ks=8), 256 threads; block: M=128, N=32, Kchunk=128.
__global__ void __launch_bounds__(256)
gemmB_kernel(const float* __restrict__ Wqkv) {
    __shared__ float Ah[128][36];    // pad 36 (36%32==4)
    __shared__ float Al[128][36];
    __shared__ float Bh[32][36];
    __shared__ float Bl[32][36];
    const int bn = blockIdx.x * 32;
    const int ks = blockIdx.y;
    const int tid  = threadIdx.x;
    const int w    = tid >> 5;
    const int lane = tid & 31;
    const int g    = lane >> 2;
    const int tg   = lane & 3;
    const int wm   = w >> 1;         // 0..3 -> m base wm*32
    const int wn   = w & 1;          // 0..1 -> n base wn*16

    float c[2][2][4];
#pragma unroll
    for (int i = 0; i < 2; i++)
#pragma unroll
        for (int j = 0; j < 2; j++)
#pragma unroll
            for (int r = 0; r < 4; r++) c[i][j][r] = 0.f;

    for (int kc = 0; kc < 4; kc++) {
        const int k0 = ks*128 + kc*32;
        // stage A (xs 128x32) hi/lo
#pragma unroll
        for (int i = 0; i < 4; i++) {
            int f = tid + 256*i;                 // 0..1023 float4 slots
            int row = f >> 3, c4 = (f & 7) * 4;
            float4 v = *(const float4*)(g_xs + (size_t)row*DD + k0 + c4);
            float hx = tf32_rna(v.x), hy = tf32_rna(v.y), hz = tf32_rna(v.z), hw = tf32_rna(v.w);
            Ah[row][c4+0] = hx; Ah[row][c4+1] = hy; Ah[row][c4+2] = hz; Ah[row][c4+3] = hw;
            Al[row][c4+0] = v.x - hx; Al[row][c4+1] = v.y - hy;
            Al[row][c4+2] = v.z - hz; Al[row][c4+3] = v.w - hw;
        }
        // stage B (Wqkv 32n x 32k) hi/lo
        {
            int row = tid >> 3, c4 = (tid & 7) * 4;
            float4 v = *(const float4*)(Wqkv + (size_t)(bn + row)*DD + k0 + c4);
            float hx = tf32_rna(v.x), hy = tf32_rna(v.y), hz = tf32_rna(v.z), hw = tf32_rna(v.w);
            Bh[row][c4+0] = hx; Bh[row][c4+1] = hy; Bh[row][c4+2] = hz; Bh[row][c4+3] = hw;
            Bl[row][c4+0] = v.x - hx; Bl[row][c4+1] = v.y - hy;
            Bl[row][c4+2] = v.z - hz; Bl[row][c4+3] = v.w - hw;
        }
        __syncthreads();
#pragma unroll
        for (int s = 0; s < 4; s++) {
            const int kc0 = s*8 + tg, kc1 = s*8 + tg + 4;
            float ah[2][4], al[2][4];
#pragma unroll
            for (int mt = 0; mt < 2; mt++) {
                int mb = wm*32 + mt*16;
                ah[mt][0] = Ah[mb+g][kc0];   ah[mt][1] = Ah[mb+g+8][kc0];
                ah[mt][2] = Ah[mb+g][kc1];   ah[mt][3] = Ah[mb+g+8][kc1];
                al[mt][0] = Al[mb+g][kc0];   al[mt][1] = Al[mb+g+8][kc0];
                al[mt][2] = Al[mb+g][kc1];   al[mt][3] = Al[mb+g+8][kc1];
            }
#pragma unroll
            for (int nt = 0; nt < 2; nt++) {
                int nr = wn*16 + nt*8 + g;
                float b0h = Bh[nr][kc0], b1h = Bh[nr][kc1];
                float b0l = Bl[nr][kc0], b1l = Bl[nr][kc1];
#pragma unroll
                for (int mt = 0; mt < 2; mt++) {
                    mma_tf32(c[mt][nt], ah[mt], b0h, b1h);
                    mma_tf32(c[mt][nt], ah[mt], b0l, b1l);
                    mma_tf32(c[mt][nt], al[mt], b0h, b1h);
                }
            }
        }
        __syncthreads();
    }
#pragma unroll
    for (int mt = 0; mt < 2; mt++)
#pragma unroll
        for (int nt = 0; nt < 2; nt++) {
            int m = wm*32 + mt*16 + g;
            int n = bn + wn*16 + nt*8 + 2*tg;
            size_t base = ((size_t)ks*128 + m)*D3 + n;
            *(float2*)&g_sp_part[base]        = make_float2(c[mt][nt][0], c[mt][nt][1]);
            *(float2*)&g_sp_part[base + 8*(size_t)D3] = make_float2(c[mt][nt][2], c[mt][nt][3]);
        }
}

__global__ void reduceB_kernel() {
    int gid = blockIdx.x * 256 + threadIdx.x;   // 393216
    float s = 0.f;
#pragma unroll
    for (int ks = 0; ks < KSPL_B; ks++) s += g_sp_part[(size_t)ks*BB*KK*D3 + gid];
    g_spec3[gid] = s;
}

// =============== 4) pulse widths ===============
__global__ void pulse_kernel(const float* __restrict__ Wqkv,
                             const float* __restrict__ W1, const float* __restrict__ b1,
                             const float* __restrict__ W2, const float* __restrict__ b2,
                             float* __restrict__ out_pw) {
    __shared__ float qm[HDIM];
    __shared__ float h1[32];
    const int bh = blockIdx.x;
    const int b = bh >> 4, h = bh & 15;
    const int d = threadIdx.x;
    const float4* wrow = (const float4*)(Wqkv + (size_t)(h*HDIM + d)*DD);
    const float4* xm   = (const float4*)(g_xm + (size_t)b*DD);
    float s = 0.f;
#pragma unroll 4
    for (int j = 0; j < DD/4; j++) {
        float4 w = wrow[j], xv = xm[j];
        s += w.x*xv.x + w.y*xv.y + w.z*xv.z + w.w*xv.w;
    }
    qm[d] = s;
    __syncthreads();
    if (d < 32) {
        float a = b1[d];
#pragma unroll
        for (int j = 0; j < HDIM; j++) a += qm[j] * W1[d*HDIM + j];
        h1[d] = a / (1.f + expf(-a));      // silu
    }
    __syncthreads();
    if (d == 0) {
        float a = b2[0];
#pragma unroll
        for (int j = 0; j < 32; j++) a += h1[j] * W2[j];
        float spl = (a > 20.f) ? a : log1pf(expf(a));  // softplus
        out_pw[bh] = 4.0f + spl;
    }
}

// =============== 5) attn + filter + scalar soliton ODE ===============
__global__ void soliton_kernel(const float* __restrict__ sfilt,
                               const float* __restrict__ pa, const float* __restrict__ pb,
                               float* __restrict__ out_resp) {
    const int bh = blockIdx.x;
    const int b = bh >> 4, h = bh & 15;
    const int k = threadIdx.x;   // 0..31
    const float* row = g_spec3 + (size_t)(b*KK + k)*D3;
    const float4* qsp = (const float4*)(row + h*HDIM);
    const float4* ksp = (const float4*)(row + DD + h*HDIM);
    float dot = 0.f;
#pragma unroll
    for (int d = 0; d < HDIM/4; d++) {
        float4 qv = qsp[d], kv = ksp[d];
        dot += qv.x*kv.x + qv.y*kv.y + qv.z*kv.z + qv.w*kv.w;
    }
    float filt = 1.f / (1.f + expf(-sfilt[h*KK + k]));
    float s = dot * 0.125f * filt;       // / sqrt(64)

    float scale = fmaxf(fabsf(s), 1e-6f);
    float sn = s / scale;
    float I  = (fabsf(s) > 0.5f) ? sn : 0.1f*sn;
    const float a = *pa, bcoef = *pb;
    const float dt = 0.2f;
    float v = 0.f, w = 0.f;
#pragma unroll
    for (int it = 0; it < 5; it++) {
        float dv = v - v*v*v*(1.f/3.f) - w + I;
        float dw = (v + a - bcoef*w) * 10.f;   // / TAU
        v = fminf(fmaxf(v + dt*dv, -3.f), 3.f);
        w = fminf(fmaxf(w + dt*dw, -3.f), 3.f);
    }
    float r = v * scale;
    g_resp[bh*KK + k]   = r;
    out_resp[bh*KK + k] = r;
}

// =============== 6) M[b] = (resp*v_spec)(32x1024) @ Wout^T, split-K ==========
// rv fused into the A-tile load. grid (nt=8, ks=8, b=4), 256 threads. FFMA2.
__global__ void __launch_bounds__(256)
gemmD_kernel(const float* __restrict__ Wout) {
    __shared__ float As[8][32];
    __shared__ float Bs[8][128];
    const int bn = blockIdx.x * 128;
    const int ks = blockIdx.y;
    const int b  = blockIdx.z;
    const int tid = threadIdx.x;
    const int tx = tid & 31;      // n: tx*4..+3
    const int my = tid >> 5;      // m: my + 8*mi
    const int lr = tid >> 1, lc = (tid & 1) << 2;

    const float* Bp = Wout + (size_t)(bn + lr)*DD + ks*128 + lc;

    ull acc2[4][2];
#pragma unroll
    for (int i = 0; i < 4; i++) { acc2[i][0] = 0ull; acc2[i][1] = 0ull; }

    for (int k0 = 0; k0 < 128; k0 += 8) {
        if (tid < 64) {
            int ar = tid >> 1, ac = (tid & 1) << 2;
            int col = ks*128 + k0 + ac;
            float4 av = *(const float4*)(g_spec3 + ((size_t)(b*KK + ar))*D3 + 2*DD + col);
            float r = g_resp[(b*HH + (col >> 6))*KK + ar];   // rv fusion
            As[ac+0][ar] = av.x * r; As[ac+1][ar] = av.y * r;
            As[ac+2][ar] = av.z * r; As[ac+3][ar] = av.w * r;
        }
        float4 bv = *(const float4*)(Bp + k0);
        Bs[lc+0][lr] = bv.x; Bs[lc+1][lr] = bv.y; Bs[lc+2][lr] = bv.z; Bs[lc+3][lr] = bv.w;
        __syncthreads();
#pragma unroll
        for (int kk = 0; kk < 8; kk++) {
            ulonglong2 rb = *(const ulonglong2*)&Bs[kk][tx*4];
            float a0 = As[kk][my], a1 = As[kk][my+8], a2 = As[kk][my+16], a3 = As[kk][my+24];
            ull p0 = pk2(a0,a0), p1 = pk2(a1,a1), p2 = pk2(a2,a2), p3 = pk2(a3,a3);
            ffma2(acc2[0][0], p0, rb.x); ffma2(acc2[0][1], p0, rb.y);
            ffma2(acc2[1][0], p1, rb.x); ffma2(acc2[1][1], p1, rb.y);
            ffma2(acc2[2][0], p2, rb.x); ffma2(acc2[2][1], p2, rb.y);
            ffma2(acc2[3][0], p3, rb.x); ffma2(acc2[3][1], p3, rb.y);
        }
        __syncthreads();
    }
#pragma unroll
    for (int mi = 0; mi < 4; mi++) {
        int m = my + 8*mi;
        *(ulonglong2*)&g_M_part[(((size_t)ks*BB + b)*KK + m)*DD + bn + tx*4] =
            make_ulonglong2(acc2[mi][0], acc2[mi][1]);
    }
}

__global__ void reduceD_kernel() {
    int gid = blockIdx.x * 256 + threadIdx.x;   // 131072
    float s = 0.f;
#pragma unroll
    for (int ks = 0; ks < KSPL_D; ks++) s += g_M_part[(size_t)ks*131072 + gid];
    g_M[gid] = s;
}

// =============== 7) out[b,t,j] = sum_k basis[b,t,k] * M[b,k,j], tensor =======
// grid (tt=64, jt=16, b=4), 256 threads; 64t x 64j tile, K=32.
__global__ void __launch_bounds__(256)
out_kernel(const float* __restrict__ basis, float* __restrict__ out) {
    __shared__ float Bh[64][36];     // basis hi (row-g pattern: pad%32==4)
    __shared__ float Bl[64][36];
    __shared__ float Mh[32][72];     // M hi (row-tg pattern: pad%32==8)
    __shared__ float Ml[32][72];
    const int tt = blockIdx.x, jt = blockIdx.y, b = blockIdx.z;
    const int t0 = tt*64, j0 = jt*64;
    const int tid  = threadIdx.x;
    const int w    = tid >> 5;
    const int lane = tid & 31;
    const int g    = lane >> 2;
    const int tg   = lane & 3;
    const int wm   = w >> 2;         // 0..1 -> t base wm*32
    const int wn   = w & 3;          // 0..3 -> j base wn*16

    // stage basis 64t x 32k hi/lo
#pragma unroll
    for (int i = 0; i < 2; i++) {
        int f = tid + 256*i;                 // 0..511 float4 slots
        int row = f >> 3, c4 = (f & 7) * 4;
        float4 v = *(const float4*)(basis + ((size_t)(b*TT + t0 + row))*KK + c4);
        float hx = tf32_rna(v.x), hy = tf32_rna(v.y), hz = tf32_rna(v.z), hw = tf32_rna(v.w);
        Bh[row][c4+0] = hx; Bh[row][c4+1] = hy; Bh[row][c4+2] = hz; Bh[row][c4+3] = hw;
        Bl[row][c4+0] = v.x - hx; Bl[row][c4+1] = v.y - hy;
        Bl[row][c4+2] = v.z - hz; Bl[row][c4+3] = v.w - hw;
    }
    // stage M 32k x 64j hi/lo
#pragma unroll
    for (int i = 0; i < 2; i++) {
        int f = tid + 256*i;                 // 0..511
        int row = f >> 4, c4 = (f & 15) * 4;
        float4 v = *(const float4*)(g_M + ((size_t)b*KK + row)*DD + j0 + c4);
        float hx = tf32_rna(v.x), hy = tf32_rna(v.y), hz = tf32_rna(v.z), hw = tf32_rna(v.w);
        Mh[row][c4+0] = hx; Mh[row][c4+1] = hy; Mh[row][c4+2] = hz; Mh[row][c4+3] = hw;
        Ml[row][c4+0] = v.x - hx; Ml[row][c4+1] = v.y - hy;
        Ml[row][c4+2] = v.z - hz; Ml[row][c4+3] = v.w - hw;
    }
    __syncthreads();

    float c[2][2][4];
#pragma unroll
    for (int i = 0; i < 2; i++)
#pragma unroll
        for (int j = 0; j < 2; j++)
#pragma unroll
            for (int r = 0; r < 4; r++) c[i][j][r] = 0.f;

#pragma unroll
    for (int s = 0; s < 4; s++) {
        const int k0 = s*8 + tg, k1 = s*8 + tg + 4;
        float ah[2][4], al[2][4];
#pragma unroll
        for (int mt = 0; mt < 2; mt++) {
            int mb = wm*32 + mt*16;
            ah[mt][0] = Bh[mb+g][k0];  ah[mt][1] = Bh[mb+g+8][k0];
            ah[mt][2] = Bh[mb+g][k1];  ah[mt][3] = Bh[mb+g+8][k1];
            al[mt][0] = Bl[mb+g][k0];  al[mt][1] = Bl[mb+g+8][k0];
            al[mt][2] = Bl[mb+g][k1];  al[mt][3] = Bl[mb+g+8][k1];
        }
#pragma unroll
        for (int nt = 0; nt < 2; nt++) {
            int nc = wn*16 + nt*8 + g;
            float b0h = Mh[k0][nc], b1h = Mh[k1][nc];
            float b0l = Ml[k0][nc], b1l = Ml[k1][nc];
#pragma unroll
            for (int mt = 0; mt < 2; mt++) {
                mma_tf32(c[mt][nt], ah[mt], b0h, b1h);
                mma_tf32(c[mt][nt], ah[mt], b0l, b1l);
                mma_tf32(c[mt][nt], al[mt], b0h, b1h);
            }
        }
    }
#pragma unroll
    for (int mt = 0; mt < 2; mt++)
#pragma unroll
        for (int nt = 0; nt < 2; nt++) {
            int t = t0 + wm*32 + mt*16 + g;
            int jc = j0 + wn*16 + nt*8 + 2*tg;
            size_t base = ((size_t)b*TT + t)*DD + jc;
            *(float2*)(out + base)        = make_float2(c[mt][nt][0], c[mt][nt][1]);
            *(float2*)(out + base + 8*(size_t)DD) = make_float2(c[mt][nt][2], c[mt][nt][3]);
        }
}

// ---------------- launch ----------------
extern "C" void kernel_launch(void* const* d_in, const int* in_sizes, int n_in,
                              void* d_out, int out_size) {
    const float* x     = (const float*)d_in[0];
    const float* basis = (const float*)d_in[1];
    const float* Wqkv  = (const float*)d_in[2];
    const float* Wout  = (const float*)d_in[3];
    const float* pa    = (const float*)d_in[4];
    const float* pb    = (const float*)d_in[5];
    const float* W1    = (const float*)d_in[6];
    const float* b1    = (const float*)d_in[7];
    const float* W2    = (const float*)d_in[8];
    const float* b2    = (const float*)d_in[9];
    const float* sfilt = (const float*)d_in[10];

    float* out      = (float*)d_out;                 // (B,T,D)
    float* out_pw   = out + (size_t)BB*TT*DD;        // (B,H)
    float* out_resp = out_pw + BH;                   // (B,H,K)

    xs_kernel<<<dim3(BB, 4, TSPLIT), 256>>>(x, basis);
    reduceA_kernel<<<512, 256>>>();
    gemmB_kernel<<<dim3(96, KSPL_B), 256>>>(Wqkv);
    reduceB_kernel<<<1536, 256>>>();
    pulse_kernel<<<BH, 64>>>(Wqkv, W1, b1, W2, b2, out_pw);
    soliton_kernel<<<BH, 32>>>(sfilt, pa, pb, out_resp);
    gemmD_kernel<<<dim3(8, KSPL_D, BB), 256>>>(Wout);
    reduceD_kernel<<<512, 256>>>();
    out_kernel<<<dim3(64, 16, BB), 256>>>(basis, out);
}

// round 9
// speedup vs baseline: 27.0304x; 1.0640x over previous
#include <cuda_runtime.h>
#include <cuda_bf16.h>
#include <math.h>
#include <stdint.h>

// Problem constants
#define BB   4
#define TT   4096
#define DD   1024
#define HH   16
#define HDIM 64
#define KK   32
#define D3   (3*DD)
#define BH   (BB*HH)

#define TSPLIT 16   // T split for xs partials
#define KSPL_B 2    // K split for spec3 GEMM (512 k each)
#define KSPL_D 8    // K split for M GEMM (128 k each)

typedef unsigned long long ull;

// ---- packed f32x2 helpers (FFMA2) ----
__device__ __forceinline__ ull pk2(float lo, float hi) {
    ull r; asm("mov.b64 %0, {%1,%2};" : "=l"(r) : "f"(lo), "f"(hi)); return r;
}
__device__ __forceinline__ void ffma2(ull& d, ull a, ull b) {
    asm("fma.rn.f32x2 %0, %1, %2, %3;" : "=l"(d) : "l"(a), "l"(b), "l"(d));
}

// ---- tf32 helpers (out_kernel) ----
__device__ __forceinline__ float tf32_rna(float f) {
    unsigned u; asm("cvt.rna.tf32.f32 %0, %1;" : "=r"(u) : "f"(f));
    return __uint_as_float(u);
}
__device__ __forceinline__ void mma_tf32(float* c, const float* a, float b0, float b1) {
    asm volatile(
        "mma.sync.aligned.m16n8k8.row.col.f32.tf32.tf32.f32 "
        "{%0,%1,%2,%3},{%4,%5,%6,%7},{%8,%9},{%0,%1,%2,%3};"
        : "+f"(c[0]), "+f"(c[1]), "+f"(c[2]), "+f"(c[3])
        : "r"(__float_as_uint(a[0])), "r"(__float_as_uint(a[1])),
          "r"(__float_as_uint(a[2])), "r"(__float_as_uint(a[3])),
          "r"(__float_as_uint(b0)),  "r"(__float_as_uint(b1)));
}

// ---- bf16 helpers ----
// cvt.rn.bf16x2.f32 d, a, b  packs a -> HIGH half, b -> LOW half
__device__ __forceinline__ unsigned pkbf(float hi, float lo) {
    unsigned r; asm("cvt.rn.bf16x2.f32 %0, %1, %2;" : "=r"(r) : "f"(hi), "f"(lo));
    return r;
}
// pair (v0 -> low/k_even, v1 -> high/k_odd): hi packed + residual packed
__device__ __forceinline__ void split2(float v0, float v1, unsigned& h, unsigned& l) {
    h = pkbf(v1, v0);
    float h0 = __uint_as_float(h << 16);
    float h1 = __uint_as_float(h & 0xffff0000u);
    l = pkbf(v1 - h1, v0 - h0);
}
// D += A(16x16) * B(16x8), bf16 inputs, fp32 accum
__device__ __forceinline__ void mma_bf16(float* c, const unsigned* a, unsigned b0, unsigned b1) {
    asm volatile(
        "mma.sync.aligned.m16n8k16.row.col.f32.bf16.bf16.f32 "
        "{%0,%1,%2,%3},{%4,%5,%6,%7},{%8,%9},{%0,%1,%2,%3};"
        : "+f"(c[0]), "+f"(c[1]), "+f"(c[2]), "+f"(c[3])
        : "r"(a[0]), "r"(a[1]), "r"(a[2]), "r"(a[3]), "r"(b0), "r"(b1));
}

// ---------------- scratch (device globals; no allocation) ----------------
__device__ float g_xs_part[TSPLIT*BB*KK*DD];
__device__ float g_xm_part[TSPLIT*BB*DD];
__device__ float g_xs[BB*KK*DD];               // (b*32+k, j)
__device__ float g_xm[BB*DD];
__device__ float g_sp_part[KSPL_B*BB*KK*D3];   // spec3 partials (2 slabs)
__device__ float g_resp[BH*KK];
__device__ float g_M_part[KSPL_D*BB*KK*DD];
__device__ float g_M[BB*KK*DD];                // (b, k, i)

// =============== 1) xs[b,k,j] = sum_t basis[b,t,k]*x[b,t,j] (+xm) ============
// bf16 3-term tensor version. grid (b=4, jt=4, ts=16), 256 threads.
__global__ void __launch_bounds__(256)
xs_kernel(const float* __restrict__ x, const float* __restrict__ basis) {
    __shared__ float xt[32][260];        // x tile fp32 (pad 260: 260%32==4)
    __shared__ unsigned bph[32][20];     // basis pairs hi [speck][tpair], pad 20
    __shared__ unsigned bpl[32][20];     // basis pairs lo
    __shared__ float xmred[4][256];
    const int b  = blockIdx.x;
    const int jt = blockIdx.y;
    const int ts = blockIdx.z;
    const int tid  = threadIdx.x;
    const int w    = tid >> 5;
    const int lane = tid & 31;
    const int g    = lane >> 2;      // 0..7
    const int tg   = lane & 3;       // 0..3
    const int j0   = jt * 256;

    float c[2][4][4];
#pragma unroll
    for (int i = 0; i < 2; i++)
#pragma unroll
        for (int j = 0; j < 4; j++)
#pragma unroll
            for (int r = 0; r < 4; r++) c[i][j][r] = 0.f;
    float4 xmacc = make_float4(0.f, 0.f, 0.f, 0.f);

    // prefetch registers
    float4 xv[8];
    float4 bv0, bv1;
    const int bt2 = tid >> 3;            // basis t-pair (tid<128)
    const int bk4 = (tid & 7) * 4;       // basis k group

    // initial prefetch (tc = 0)
    {
        const int t0 = ts*256;
#pragma unroll
        for (int i = 0; i < 8; i++) {
            int f = tid + 256*i;
            int row = f >> 6, c4 = (f & 63) * 4;
            xv[i] = *(const float4*)(x + ((size_t)(b*TT + t0 + row))*DD + j0 + c4);
        }
        if (tid < 128) {
            bv0 = *(const float4*)(basis + ((size_t)(b*TT + t0 + 2*bt2  ))*KK + bk4);
            bv1 = *(const float4*)(basis + ((size_t)(b*TT + t0 + 2*bt2+1))*KK + bk4);
        }
    }

    for (int tc = 0; tc < 8; tc++) {
        // store staged tiles from registers
#pragma unroll
        for (int i = 0; i < 8; i++) {
            int f = tid + 256*i;
            int row = f >> 6, c4 = (f & 63) * 4;
            *(float4*)&xt[row][c4] = xv[i];
            xmacc.x += xv[i].x; xmacc.y += xv[i].y; xmacc.z += xv[i].z; xmacc.w += xv[i].w;
        }
        if (tid < 128) {
            float e0[4] = {bv0.x, bv0.y, bv0.z, bv0.w};
            float e1[4] = {bv1.x, bv1.y, bv1.z, bv1.w};
#pragma unroll
            for (int kk = 0; kk < 4; kk++) {
                unsigned h, l;
                split2(e0[kk], e1[kk], h, l);
                bph[bk4 + kk][bt2] = h;
                bpl[bk4 + kk][bt2] = l;
            }
        }
        __syncthreads();

        // prefetch next tc
        if (tc < 7) {
            const int t0 = ts*256 + (tc+1)*32;
#pragma unroll
            for (int i = 0; i < 8; i++) {
                int f = tid + 256*i;
                int row = f >> 6, c4 = (f & 63) * 4;
                xv[i] = *(const float4*)(x + ((size_t)(b*TT + t0 + row))*DD + j0 + c4);
            }
            if (tid < 128) {
                bv0 = *(const float4*)(basis + ((size_t)(b*TT + t0 + 2*bt2  ))*KK + bk4);
                bv1 = *(const float4*)(basis + ((size_t)(b*TT + t0 + 2*bt2+1))*KK + bk4);
            }
        }

        // compute: 2 k16-steps per tc
#pragma unroll
        for (int s = 0; s < 2; s++) {
            unsigned ah[2][4], al[2][4];
#pragma unroll
            for (int mt = 0; mt < 2; mt++) {
                int mb = mt*16;
                ah[mt][0] = bph[mb+g  ][s*8+tg];   ah[mt][1] = bph[mb+g+8][s*8+tg];
                ah[mt][2] = bph[mb+g  ][s*8+tg+4]; ah[mt][3] = bph[mb+g+8][s*8+tg+4];
                al[mt][0] = bpl[mb+g  ][s*8+tg];   al[mt][1] = bpl[mb+g+8][s*8+tg];
                al[mt][2] = bpl[mb+g  ][s*8+tg+4]; al[mt][3] = bpl[mb+g+8][s*8+tg+4];
            }
#pragma unroll
            for (int nt = 0; nt < 4; nt++) {
                int jl = w*32 + nt*8 + g;
                int tb = s*16 + 2*tg;
                float x0 = xt[tb  ][jl], x1 = xt[tb+1][jl];
                float x2 = xt[tb+8][jl], x3 = xt[tb+9][jl];
                unsigned b0h, b0l, b1h, b1l;
                split2(x0, x1, b0h, b0l);
                split2(x2, x3, b1h, b1l);
#pragma unroll
                for (int mt = 0; mt < 2; mt++) {
                    mma_bf16(c[mt][nt], ah[mt], b0h, b1h);
                    mma_bf16(c[mt][nt], ah[mt], b0l, b1l);
                    mma_bf16(c[mt][nt], al[mt], b0h, b1h);
                }
            }
        }
        __syncthreads();
    }

    // store C -> g_xs_part
#pragma unroll
    for (int mt = 0; mt < 2; mt++)
#pragma unroll
        for (int nt = 0; nt < 4; nt++) {
            int krow = mt*16 + g;
            int jc = j0 + w*32 + nt*8 + 2*tg;
            size_t base = (((size_t)ts*BB + b)*KK + krow)*DD + jc;
            *(float2*)&g_xs_part[base]        = make_float2(c[mt][nt][0], c[mt][nt][1]);
            *(float2*)&g_xs_part[base + 8*DD] = make_float2(c[mt][nt][2], c[mt][nt][3]);
        }
    // xm partial reduction
    *(float4*)&xmred[tid >> 6][(tid & 63) * 4] = xmacc;
    __syncthreads();
    if (tid < 64) {
        float4 s = make_float4(0.f, 0.f, 0.f, 0.f);
#pragma unroll
        for (int r = 0; r < 4; r++) {
            float4 v = *(const float4*)&xmred[r][tid*4];
            s.x += v.x; s.y += v.y; s.z += v.z; s.w += v.w;
        }
        *(float4*)&g_xm_part[((size_t)ts*BB + b)*DD + j0 + tid*4] = s;
    }
}

// =============== 2) reduce xs partials + xm ===============
__global__ void reduceA_kernel() {
    int gid = blockIdx.x * 256 + threadIdx.x;   // 131072
    float s = 0.f;
#pragma unroll
    for (int ts = 0; ts < TSPLIT; ts++) s += g_xs_part[(size_t)ts*131072 + gid];
    g_xs[gid] = s;
    if (gid < BB*DD) {
        float m = 0.f;
#pragma unroll
        for (int ts = 0; ts < TSPLIT; ts++) m += g_xm_part[(size_t)ts*BB*DD + gid];
        g_xm[gid] = m * (1.0f / (float)TT);
    }
}

// =============== 3) spec3 partials = xs(128x1024) @ Wqkv^T, bf16 3-term ======
// grid (nt=96, ks=2), 256 threads; block M=128, N=32, K=512 in chunks of 64.
__global__ void __launch_bounds__(256)
gemmB_kernel(const float* __restrict__ Wqkv) {
    __shared__ unsigned Aph[128][36];    // [m][kpair], pad 36 (36%32==4)
    __shared__ unsigned Apl[128][36];
    __shared__ unsigned Bph[32][36];
    __shared__ unsigned Bpl[32][36];
    const int bn = blockIdx.x * 32;
    const int ks = blockIdx.y;
    const int tid  = threadIdx.x;
    const int w    = tid >> 5;
    const int lane = tid & 31;
    const int g    = lane >> 2;
    const int tg   = lane & 3;
    const int wm   = w >> 1;         // 0..3 -> m base wm*32
    const int wn   = w & 1;          // 0..1 -> n base wn*16

    float c[2][2][4];
#pragma unroll
    for (int i = 0; i < 2; i++)
#pragma unroll
        for (int j = 0; j < 2; j++)
#pragma unroll
            for (int r = 0; r < 4; r++) c[i][j][r] = 0.f;

    for (int kc = 0; kc < 8; kc++) {
        const int k0 = ks*512 + kc*64;
        // stage A (g_xs 128m x 64k): 2048 float4 items
#pragma unroll
        for (int i = 0; i < 8; i++) {
            int f = tid + 256*i;
            int m = f >> 4, kg = f & 15;
            float4 v = *(const float4*)(g_xs + (size_t)m*DD + k0 + kg*4);
            unsigned h0, l0, h1, l1;
            split2(v.x, v.y, h0, l0);
            split2(v.z, v.w, h1, l1);
            Aph[m][kg*2] = h0; Aph[m][kg*2+1] = h1;
            Apl[m][kg*2] = l0; Apl[m][kg*2+1] = l1;
        }
        // stage B (Wqkv 32n x 64k): 512 items
#pragma unroll
        for (int i = 0; i < 2; i++) {
            int f = tid + 256*i;
            int n = f >> 4, kg = f & 15;
            float4 v = *(const float4*)(Wqkv + (size_t)(bn + n)*DD + k0 + kg*4);
            unsigned h0, l0, h1, l1;
            split2(v.x, v.y, h0, l0);
            split2(v.z, v.w, h1, l1);
            Bph[n][kg*2] = h0; Bph[n][kg*2+1] = h1;
            Bpl[n][kg*2] = l0; Bpl[n][kg*2+1] = l1;
        }
        __syncthreads();
#pragma unroll
        for (int s = 0; s < 4; s++) {
            unsigned ah[2][4], al[2][4];
#pragma unroll
            for (int mt = 0; mt < 2; mt++) {
                int mb = wm*32 + mt*16;
                ah[mt][0] = Aph[mb+g  ][s*8+tg];   ah[mt][1] = Aph[mb+g+8][s*8+tg];
                ah[mt][2] = Aph[mb+g  ][s*8+tg+4]; ah[mt][3] = Aph[mb+g+8][s*8+tg+4];
                al[mt][0] = Apl[mb+g  ][s*8+tg];   al[mt][1] = Apl[mb+g+8][s*8+tg];
                al[mt][2] = Apl[mb+g  ][s*8+tg+4]; al[mt][3] = Apl[mb+g+8][s*8+tg+4];
            }
#pragma unroll
            for (int nt = 0; nt < 2; nt++) {
                int nr = wn*16 + nt*8 + g;
                unsigned b0h = Bph[nr][s*8+tg], b1h = Bph[nr][s*8+tg+4];
                unsigned b0l = Bpl[nr][s*8+tg], b1l = Bpl[nr][s*8+tg+4];
#pragma unroll
                for (int mt = 0; mt < 2; mt++) {
                    mma_bf16(c[mt][nt], ah[mt], b0h, b1h);
                    mma_bf16(c[mt][nt], ah[mt], b0l, b1l);
                    mma_bf16(c[mt][nt], al[mt], b0h, b1h);
                }
            }
        }
        __syncthreads();
    }
#pragma unroll
    for (int mt = 0; mt < 2; mt++)
#pragma unroll
        for (int nt = 0; nt < 2; nt++) {
            int m = wm*32 + mt*16 + g;
            int n = bn + wn*16 + nt*8 + 2*tg;
            size_t base = ((size_t)ks*128 + m)*D3 + n;
            *(float2*)&g_sp_part[base]                = make_float2(c[mt][nt][0], c[mt][nt][1]);
            *(float2*)&g_sp_part[base + 8*(size_t)D3] = make_float2(c[mt][nt][2], c[mt][nt][3]);
        }
}

// =============== 4) fused pulse widths + soliton ODE ===============
// grid 128 x 64 thr. blocks [0,64): soliton (bh=bid); [64,128): pulse (bh=bid-64)
__global__ void ps_kernel(const float* __restrict__ Wqkv,
                          const float* __restrict__ W1, const float* __restrict__ b1,
                          const float* __restrict__ W2, const float* __restrict__ b2,
                          const float* __restrict__ sfilt,
                          const float* __restrict__ pa, const float* __restrict__ pb,
                          float* __restrict__ out_pw, float* __restrict__ out_resp) {
    if (blockIdx.x < 64) {
        // ---- soliton ----
        const int bh = blockIdx.x;
        const int b = bh >> 4, h = bh & 15;
        const int k = threadIdx.x;
        if (k >= 32) return;
        const size_t m = (size_t)(b*KK + k);
        const float* P0 = g_sp_part + m*D3;
        const float* P1 = g_sp_part + (128 + m)*D3;
        float dot = 0.f;
#pragma unroll
        for (int d = 0; d < HDIM/4; d++) {
            float4 q0 = *(const float4*)(P0 + h*HDIM + d*4);
            float4 q1 = *(const float4*)(P1 + h*HDIM + d*4);
            float4 k0 = *(const float4*)(P0 + DD + h*HDIM + d*4);
            float4 k1 = *(const float4*)(P1 + DD + h*HDIM + d*4);
            dot += (q0.x+q1.x)*(k0.x+k1.x) + (q0.y+q1.y)*(k0.y+k1.y)
                 + (q0.z+q1.z)*(k0.z+k1.z) + (q0.w+q1.w)*(k0.w+k1.w);
        }
        float filt = 1.f / (1.f + expf(-sfilt[h*KK + k]));
        float s = dot * 0.125f * filt;

        float scale = fmaxf(fabsf(s), 1e-6f);
        float sn = s / scale;
        float I  = (fabsf(s) > 0.5f) ? sn : 0.1f*sn;
        const float a = *pa, bcoef = *pb;
        const float dt = 0.2f;
        float v = 0.f, w = 0.f;
#pragma unroll
        for (int it = 0; it < 5; it++) {
            float dv = v - v*v*v*(1.f/3.f) - w + I;
            float dw = (v + a - bcoef*w) * 10.f;
            v = fminf(fmaxf(v + dt*dv, -3.f), 3.f);
            w = fminf(fmaxf(w + dt*dw, -3.f), 3.f);
        }
        float r = v * scale;
        g_resp[bh*KK + k]   = r;
        out_resp[bh*KK + k] = r;
    } else {
        // ---- pulse widths ----
        __shared__ float qm[HDIM];
        __shared__ float h1[32];
        const int bh = blockIdx.x - 64;
        const int b = bh >> 4, h = bh & 15;
        const int d = threadIdx.x;
        const float4* wrow = (const float4*)(Wqkv + (size_t)(h*HDIM + d)*DD);
        const float4* xm   = (const float4*)(g_xm + (size_t)b*DD);
        float s = 0.f;
#pragma unroll 4
        for (int j = 0; j < DD/4; j++) {
            float4 w = wrow[j], xv = xm[j];
            s += w.x*xv.x + w.y*xv.y + w.z*xv.z + w.w*xv.w;
        }
        qm[d] = s;
        __syncthreads();
        if (d < 32) {
            float a = b1[d];
#pragma unroll
            for (int j = 0; j < HDIM; j++) a += qm[j] * W1[d*HDIM + j];
            h1[d] = a / (1.f + expf(-a));
        }
        __syncthreads();
        if (d == 0) {
            float a = b2[0];
#pragma unroll
            for (int j = 0; j < 32; j++) a += h1[j] * W2[j];
            float spl = (a > 20.f) ? a : log1pf(expf(a));
            out_pw[bh] = 4.0f + spl;
        }
    }
}

// =============== 5) M[b] = (resp*v_spec)(32x1024) @ Wout^T, split-K ==========
// v_spec reduction (2 partials) + rv fused into the A-tile load. FFMA2.
__global__ void __launch_bounds__(256)
gemmD_kernel(const float* __restrict__ Wout) {
    __shared__ float As[8][32];
    __shared__ float Bs[8][128];
    const int bn = blockIdx.x * 128;
    const int ks = blockIdx.y;
    const int b  = blockIdx.z;
    const int tid = threadIdx.x;
    const int tx = tid & 31;
    const int my = tid >> 5;
    const int lr = tid >> 1, lc = (tid & 1) << 2;

    const float* Bp = Wout + (size_t)(bn + lr)*DD + ks*128 + lc;

    ull acc2[4][2];
#pragma unroll
    for (int i = 0; i < 4; i++) { acc2[i][0] = 0ull; acc2[i][1] = 0ull; }

    for (int k0 = 0; k0 < 128; k0 += 8) {
        if (tid < 64) {
            int ar = tid >> 1, ac = (tid & 1) << 2;
            int col = ks*128 + k0 + ac;
            size_t m = (size_t)(b*KK + ar);
            float4 a0 = *(const float4*)(g_sp_part + m*D3 + 2*DD + col);
            float4 a1 = *(const float4*)(g_sp_part + (128 + m)*D3 + 2*DD + col);
            float r = g_resp[(b*HH + (col >> 6))*KK + ar];
            As[ac+0][ar] = (a0.x + a1.x) * r; As[ac+1][ar] = (a0.y + a1.y) * r;
            As[ac+2][ar] = (a0.z + a1.z) * r; As[ac+3][ar] = (a0.w + a1.w) * r;
        }
        float4 bv = *(const float4*)(Bp + k0);
        Bs[lc+0][lr] = bv.x; Bs[lc+1][lr] = bv.y; Bs[lc+2][lr] = bv.z; Bs[lc+3][lr] = bv.w;
        __syncthreads();
#pragma unroll
        for (int kk = 0; kk < 8; kk++) {
            ulonglong2 rb = *(const ulonglong2*)&Bs[kk][tx*4];
            float a0 = As[kk][my], a1 = As[kk][my+8], a2 = As[kk][my+16], a3 = As[kk][my+24];
            ull p0 = pk2(a0,a0), p1 = pk2(a1,a1), p2 = pk2(a2,a2), p3 = pk2(a3,a3);
            ffma2(acc2[0][0], p0, rb.x); ffma2(acc2[0][1], p0, rb.y);
            ffma2(acc2[1][0], p1, rb.x); ffma2(acc2[1][1], p1, rb.y);
            ffma2(acc2[2][0], p2, rb.x); ffma2(acc2[2][1], p2, rb.y);
            ffma2(acc2[3][0], p3, rb.x); ffma2(acc2[3][1], p3, rb.y);
        }
        __syncthreads();
    }
#pragma unroll
    for (int mi = 0; mi < 4; mi++) {
        int m = my + 8*mi;
        *(ulonglong2*)&g_M_part[(((size_t)ks*BB + b)*KK + m)*DD + bn + tx*4] =
            make_ulonglong2(acc2[mi][0], acc2[mi][1]);
    }
}

__global__ void reduceD_kernel() {
    int gid = blockIdx.x * 256 + threadIdx.x;   // 131072
    float s = 0.f;
#pragma unroll
    for (int ks = 0; ks < KSPL_D; ks++) s += g_M_part[(size_t)ks*131072 + gid];
    g_M[gid] = s;
}

// =============== 6) out[b,t,j] = sum_k basis[b,t,k] * M[b,k,j], tf32 tensor ==
__global__ void __launch_bounds__(256)
out_kernel(const float* __restrict__ basis, float* __restrict__ out) {
    __shared__ float Bh[64][36];
    __shared__ float Bl[64][36];
    __shared__ float Mh[32][72];
    __shared__ float Ml[32][72];
    const int tt = blockIdx.x, jt = blockIdx.y, b = blockIdx.z;
    const int t0 = tt*64, j0 = jt*64;
    const int tid  = threadIdx.x;
    const int w    = tid >> 5;
    const int lane = tid & 31;
    const int g    = lane >> 2;
    const int tg   = lane & 3;
    const int wm   = w >> 2;
    const int wn   = w & 3;

#pragma unroll
    for (int i = 0; i < 2; i++) {
        int f = tid + 256*i;
        int row = f >> 3, c4 = (f & 7) * 4;
        float4 v = *(const float4*)(basis + ((size_t)(b*TT + t0 + row))*KK + c4);
        float hx = tf32_rna(v.x), hy = tf32_rna(v.y), hz = tf32_rna(v.z), hw = tf32_rna(v.w);
        Bh[row][c4+0] = hx; Bh[row][c4+1] = hy; Bh[row][c4+2] = hz; Bh[row][c4+3] = hw;
        Bl[row][c4+0] = v.x - hx; Bl[row][c4+1] = v.y - hy;
        Bl[row][c4+2] = v.z - hz; Bl[row][c4+3] = v.w - hw;
    }
#pragma unroll
    for (int i = 0; i < 2; i++) {
        int f = tid + 256*i;
        int row = f >> 4, c4 = (f & 15) * 4;
        float4 v = *(const float4*)(g_M + ((size_t)b*KK + row)*DD + j0 + c4);
        float hx = tf32_rna(v.x), hy = tf32_rna(v.y), hz = tf32_rna(v.z), hw = tf32_rna(v.w);
        Mh[row][c4+0] = hx; Mh[row][c4+1] = hy; Mh[row][c4+2] = hz; Mh[row][c4+3] = hw;
        Ml[row][c4+0] = v.x - hx; Ml[row][c4+1] = v.y - hy;
        Ml[row][c4+2] = v.z - hz; Ml[row][c4+3] = v.w - hw;
    }
    __syncthreads();

    float c[2][2][4];
#pragma unroll
    for (int i = 0; i < 2; i++)
#pragma unroll
        for (int j = 0; j < 2; j++)
#pragma unroll
            for (int r = 0; r < 4; r++) c[i][j][r] = 0.f;

#pragma unroll
    for (int s = 0; s < 4; s++) {
        const int k0 = s*8 + tg, k1 = s*8 + tg + 4;
        float ah[2][4], al[2][4];
#pragma unroll
        for (int mt = 0; mt < 2; mt++) {
            int mb = wm*32 + mt*16;
            ah[mt][0] = Bh[mb+g][k0];  ah[mt][1] = Bh[mb+g+8][k0];
            ah[mt][2] = Bh[mb+g][k1];  ah[mt][3] = Bh[mb+g+8][k1];
            al[mt][0] = Bl[mb+g][k0];  al[mt][1] = Bl[mb+g+8][k0];
            al[mt][2] = Bl[mb+g][k1];  al[mt][3] = Bl[mb+g+8][k1];
        }
#pragma unroll
        for (int nt = 0; nt < 2; nt++) {
            int nc = wn*16 + nt*8 + g;
            float b0h = Mh[k0][nc], b1h = Mh[k1][nc];
            float b0l = Ml[k0][nc], b1l = Ml[k1][nc];
#pragma unroll
            for (int mt = 0; mt < 2; mt++) {
                mma_tf32(c[mt][nt], ah[mt], b0h, b1h);
                mma_tf32(c[mt][nt], ah[mt], b0l, b1l);
                mma_tf32(c[mt][nt], al[mt], b0h, b1h);
            }
        }
    }
#pragma unroll
    for (int mt = 0; mt < 2; mt++)
#pragma unroll
        for (int nt = 0; nt < 2; nt++) {
            int t = t0 + wm*32 + mt*16 + g;
            int jc = j0 + wn*16 + nt*8 + 2*tg;
            size_t base = ((size_t)b*TT + t)*DD + jc;
            *(float2*)(out + base)                = make_float2(c[mt][nt][0], c[mt][nt][1]);
            *(float2*)(out + base + 8*(size_t)DD) = make_float2(c[mt][nt][2], c[mt][nt][3]);
        }
}

// ---------------- launch ----------------
extern "C" void kernel_launch(void* const* d_in, const int* in_sizes, int n_in,
                              void* d_out, int out_size) {
    const float* x     = (const float*)d_in[0];
    const float* basis = (const float*)d_in[1];
    const float* Wqkv  = (const float*)d_in[2];
    const float* Wout  = (const float*)d_in[3];
    const float* pa    = (const float*)d_in[4];
    const float* pb    = (const float*)d_in[5];
    const float* W1    = (const float*)d_in[6];
    const float* b1    = (const float*)d_in[7];
    const float* W2    = (const float*)d_in[8];
    const float* b2    = (const float*)d_in[9];
    const float* sfilt = (const float*)d_in[10];

    float* out      = (float*)d_out;                 // (B,T,D)
    float* out_pw   = out + (size_t)BB*TT*DD;        // (B,H)
    float* out_resp = out_pw + BH;                   // (B,H,K)

    xs_kernel<<<dim3(BB, 4, TSPLIT), 256>>>(x, basis);
    reduceA_kernel<<<512, 256>>>();
    gemmB_kernel<<<dim3(96, KSPL_B), 256>>>(Wqkv);
    ps_kernel<<<128, 64>>>(Wqkv, W1, b1, W2, b2, sfilt, pa, pb, out_pw, out_resp);
    gemmD_kernel<<<dim3(8, KSPL_D, BB), 256>>>(Wout);
    reduceD_kernel<<<512, 256>>>();
    out_kernel<<<dim3(64, 16, BB), 256>>>(basis, out);
}

// round 10
// speedup vs baseline: 31.9994x; 1.1838x over previous
#include <cuda_runtime.h>
#include <cuda_bf16.h>
#include <math.h>
#include <stdint.h>

// Problem constants
#define BB   4
#define TT   4096
#define DD   1024
#define HH   16
#define HDIM 64
#define KK   32
#define D3   (3*DD)
#define BH   (BB*HH)

#define TSPLIT 16   // T split for xs partials
#define KSPL_B 2    // K split for spec3 GEMM (512 k each)
#define KSPL_D 8    // K split for M GEMM (128 k each)

typedef unsigned long long ull;

// ---- packed f32x2 helpers (FFMA2) ----
__device__ __forceinline__ ull pk2(float lo, float hi) {
    ull r; asm("mov.b64 %0, {%1,%2};" : "=l"(r) : "f"(lo), "f"(hi)); return r;
}
__device__ __forceinline__ void ffma2(ull& d, ull a, ull b) {
    asm("fma.rn.f32x2 %0, %1, %2, %3;" : "=l"(d) : "l"(a), "l"(b), "l"(d));
}

// ---- tf32 helpers (out_kernel) ----
__device__ __forceinline__ float tf32_rna(float f) {
    unsigned u; asm("cvt.rna.tf32.f32 %0, %1;" : "=r"(u) : "f"(f));
    return __uint_as_float(u);
}
__device__ __forceinline__ void mma_tf32(float* c, const float* a, float b0, float b1) {
    asm volatile(
        "mma.sync.aligned.m16n8k8.row.col.f32.tf32.tf32.f32 "
        "{%0,%1,%2,%3},{%4,%5,%6,%7},{%8,%9},{%0,%1,%2,%3};"
        : "+f"(c[0]), "+f"(c[1]), "+f"(c[2]), "+f"(c[3])
        : "r"(__float_as_uint(a[0])), "r"(__float_as_uint(a[1])),
          "r"(__float_as_uint(a[2])), "r"(__float_as_uint(a[3])),
          "r"(__float_as_uint(b0)),  "r"(__float_as_uint(b1)));
}

// ---- bf16 helpers ----
__device__ __forceinline__ unsigned pkbf(float hi, float lo) {
    unsigned r; asm("cvt.rn.bf16x2.f32 %0, %1, %2;" : "=r"(r) : "f"(hi), "f"(lo));
    return r;
}
__device__ __forceinline__ void split2(float v0, float v1, unsigned& h, unsigned& l) {
    h = pkbf(v1, v0);
    float h0 = __uint_as_float(h << 16);
    float h1 = __uint_as_float(h & 0xffff0000u);
    l = pkbf(v1 - h1, v0 - h0);
}
__device__ __forceinline__ void mma_bf16(float* c, const unsigned* a, unsigned b0, unsigned b1) {
    asm volatile(
        "mma.sync.aligned.m16n8k16.row.col.f32.bf16.bf16.f32 "
        "{%0,%1,%2,%3},{%4,%5,%6,%7},{%8,%9},{%0,%1,%2,%3};"
        : "+f"(c[0]), "+f"(c[1]), "+f"(c[2]), "+f"(c[3])
        : "r"(a[0]), "r"(a[1]), "r"(a[2]), "r"(a[3]), "r"(b0), "r"(b1));
}

// ---------------- scratch (device globals; no allocation) ----------------
__device__ float g_xs_part[TSPLIT*BB*KK*DD];
__device__ float g_xm_part[TSPLIT*BB*DD];
__device__ float g_xs[BB*KK*DD];               // (b*32+k, j)
__device__ float g_xm[BB*DD];
__device__ float g_qm[BB*DD];                  // qm[b, h*64+d]
__device__ float g_sp_part[KSPL_B*BB*KK*D3];   // spec3 partials (2 slabs)
__device__ float g_resp[BH*KK];
__device__ float g_M_part[KSPL_D*BB*KK*DD];
__device__ float g_M[BB*KK*DD];                // (b, k, i)

// =============== 1) xs[b,k,j] = sum_t basis[b,t,k]*x[b,t,j] (+xm) ============
// bf16 3-term tensor version. grid (b=4, jt=4, ts=16), 256 threads.
__global__ void __launch_bounds__(256)
xs_kernel(const float* __restrict__ x, const float* __restrict__ basis) {
    __shared__ float xt[32][260];        // x tile fp32 (pad 260: 260%32==4)
    __shared__ unsigned bph[32][20];     // basis pairs hi [speck][tpair], pad 20
    __shared__ unsigned bpl[32][20];     // basis pairs lo
    __shared__ float xmred[4][256];
    const int b  = blockIdx.x;
    const int jt = blockIdx.y;
    const int ts = blockIdx.z;
    const int tid  = threadIdx.x;
    const int w    = tid >> 5;
    const int lane = tid & 31;
    const int g    = lane >> 2;      // 0..7
    const int tg   = lane & 3;       // 0..3
    const int j0   = jt * 256;

    float c[2][4][4];
#pragma unroll
    for (int i = 0; i < 2; i++)
#pragma unroll
        for (int j = 0; j < 4; j++)
#pragma unroll
            for (int r = 0; r < 4; r++) c[i][j][r] = 0.f;
    float4 xmacc = make_float4(0.f, 0.f, 0.f, 0.f);

    float4 xv[8];
    float4 bv0, bv1;
    const int bt2 = tid >> 3;
    const int bk4 = (tid & 7) * 4;

    {
        const int t0 = ts*256;
#pragma unroll
        for (int i = 0; i < 8; i++) {
            int f = tid + 256*i;
            int row = f >> 6, c4 = (f & 63) * 4;
            xv[i] = *(const float4*)(x + ((size_t)(b*TT + t0 + row))*DD + j0 + c4);
        }
        if (tid < 128) {
            bv0 = *(const float4*)(basis + ((size_t)(b*TT + t0 + 2*bt2  ))*KK + bk4);
            bv1 = *(const float4*)(basis + ((size_t)(b*TT + t0 + 2*bt2+1))*KK + bk4);
        }
    }

    for (int tc = 0; tc < 8; tc++) {
#pragma unroll
        for (int i = 0; i < 8; i++) {
            int f = tid + 256*i;
            int row = f >> 6, c4 = (f & 63) * 4;
            *(float4*)&xt[row][c4] = xv[i];
            xmacc.x += xv[i].x; xmacc.y += xv[i].y; xmacc.z += xv[i].z; xmacc.w += xv[i].w;
        }
        if (tid < 128) {
            float e0[4] = {bv0.x, bv0.y, bv0.z, bv0.w};
            float e1[4] = {bv1.x, bv1.y, bv1.z, bv1.w};
#pragma unroll
            for (int kk = 0; kk < 4; kk++) {
                unsigned h, l;
                split2(e0[kk], e1[kk], h, l);
                bph[bk4 + kk][bt2] = h;
                bpl[bk4 + kk][bt2] = l;
            }
        }
        __syncthreads();

        if (tc < 7) {
            const int t0 = ts*256 + (tc+1)*32;
#pragma unroll
            for (int i = 0; i < 8; i++) {
                int f = tid + 256*i;
                int row = f >> 6, c4 = (f & 63) * 4;
                xv[i] = *(const float4*)(x + ((size_t)(b*TT + t0 + row))*DD + j0 + c4);
            }
            if (tid < 128) {
                bv0 = *(const float4*)(basis + ((size_t)(b*TT + t0 + 2*bt2  ))*KK + bk4);
                bv1 = *(const float4*)(basis + ((size_t)(b*TT + t0 + 2*bt2+1))*KK + bk4);
            }
        }

#pragma unroll
        for (int s = 0; s < 2; s++) {
            unsigned ah[2][4], al[2][4];
#pragma unroll
            for (int mt = 0; mt < 2; mt++) {
                int mb = mt*16;
                ah[mt][0] = bph[mb+g  ][s*8+tg];   ah[mt][1] = bph[mb+g+8][s*8+tg];
                ah[mt][2] = bph[mb+g  ][s*8+tg+4]; ah[mt][3] = bph[mb+g+8][s*8+tg+4];
                al[mt][0] = bpl[mb+g  ][s*8+tg];   al[mt][1] = bpl[mb+g+8][s*8+tg];
                al[mt][2] = bpl[mb+g  ][s*8+tg+4]; al[mt][3] = bpl[mb+g+8][s*8+tg+4];
            }
#pragma unroll
            for (int nt = 0; nt < 4; nt++) {
                int jl = w*32 + nt*8 + g;
                int tb = s*16 + 2*tg;
                float x0 = xt[tb  ][jl], x1 = xt[tb+1][jl];
                float x2 = xt[tb+8][jl], x3 = xt[tb+9][jl];
                unsigned b0h, b0l, b1h, b1l;
                split2(x0, x1, b0h, b0l);
                split2(x2, x3, b1h, b1l);
#pragma unroll
                for (int mt = 0; mt < 2; mt++) {
                    mma_bf16(c[mt][nt], ah[mt], b0h, b1h);
                    mma_bf16(c[mt][nt], ah[mt], b0l, b1l);
                    mma_bf16(c[mt][nt], al[mt], b0h, b1h);
                }
            }
        }
        __syncthreads();
    }

#pragma unroll
    for (int mt = 0; mt < 2; mt++)
#pragma unroll
        for (int nt = 0; nt < 4; nt++) {
            int krow = mt*16 + g;
            int jc = j0 + w*32 + nt*8 + 2*tg;
            size_t base = (((size_t)ts*BB + b)*KK + krow)*DD + jc;
            *(float2*)&g_xs_part[base]        = make_float2(c[mt][nt][0], c[mt][nt][1]);
            *(float2*)&g_xs_part[base + 8*DD] = make_float2(c[mt][nt][2], c[mt][nt][3]);
        }
    *(float4*)&xmred[tid >> 6][(tid & 63) * 4] = xmacc;
    __syncthreads();
    if (tid < 64) {
        float4 s = make_float4(0.f, 0.f, 0.f, 0.f);
#pragma unroll
        for (int r = 0; r < 4; r++) {
            float4 v = *(const float4*)&xmred[r][tid*4];
            s.x += v.x; s.y += v.y; s.z += v.z; s.w += v.w;
        }
        *(float4*)&g_xm_part[((size_t)ts*BB + b)*DD + j0 + tid*4] = s;
    }
}

// =============== 2) reduce xs partials + xm ===============
__global__ void reduceA_kernel() {
    int gid = blockIdx.x * 256 + threadIdx.x;   // 131072
    float s = 0.f;
#pragma unroll
    for (int ts = 0; ts < TSPLIT; ts++) s += g_xs_part[(size_t)ts*131072 + gid];
    g_xs[gid] = s;
    if (gid < BB*DD) {
        float m = 0.f;
#pragma unroll
        for (int ts = 0; ts < TSPLIT; ts++) m += g_xm_part[(size_t)ts*BB*DD + gid];
        g_xm[gid] = m * (1.0f / (float)TT);
    }
}

// =============== 3) spec3 partials = xs(128x1024) @ Wqkv^T, bf16 3-term ======
__global__ void __launch_bounds__(256)
gemmB_kernel(const float* __restrict__ Wqkv) {
    __shared__ unsigned Aph[128][36];
    __shared__ unsigned Apl[128][36];
    __shared__ unsigned Bph[32][36];
    __shared__ unsigned Bpl[32][36];
    const int bn = blockIdx.x * 32;
    const int ks = blockIdx.y;
    const int tid  = threadIdx.x;
    const int w    = tid >> 5;
    const int lane = tid & 31;
    const int g    = lane >> 2;
    const int tg   = lane & 3;
    const int wm   = w >> 1;
    const int wn   = w & 1;

    float c[2][2][4];
#pragma unroll
    for (int i = 0; i < 2; i++)
#pragma unroll
        for (int j = 0; j < 2; j++)
#pragma unroll
            for (int r = 0; r < 4; r++) c[i][j][r] = 0.f;

    for (int kc = 0; kc < 8; kc++) {
        const int k0 = ks*512 + kc*64;
#pragma unroll
        for (int i = 0; i < 8; i++) {
            int f = tid + 256*i;
            int m = f >> 4, kg = f & 15;
            float4 v = *(const float4*)(g_xs + (size_t)m*DD + k0 + kg*4);
            unsigned h0, l0, h1, l1;
            split2(v.x, v.y, h0, l0);
            split2(v.z, v.w, h1, l1);
            Aph[m][kg*2] = h0; Aph[m][kg*2+1] = h1;
            Apl[m][kg*2] = l0; Apl[m][kg*2+1] = l1;
        }
#pragma unroll
        for (int i = 0; i < 2; i++) {
            int f = tid + 256*i;
            int n = f >> 4, kg = f & 15;
            float4 v = *(const float4*)(Wqkv + (size_t)(bn + n)*DD + k0 + kg*4);
            unsigned h0, l0, h1, l1;
            split2(v.x, v.y, h0, l0);
            split2(v.z, v.w, h1, l1);
            Bph[n][kg*2] = h0; Bph[n][kg*2+1] = h1;
            Bpl[n][kg*2] = l0; Bpl[n][kg*2+1] = l1;
        }
        __syncthreads();
#pragma unroll
        for (int s = 0; s < 4; s++) {
            unsigned ah[2][4], al[2][4];
#pragma unroll
            for (int mt = 0; mt < 2; mt++) {
                int mb = wm*32 + mt*16;
                ah[mt][0] = Aph[mb+g  ][s*8+tg];   ah[mt][1] = Aph[mb+g+8][s*8+tg];
                ah[mt][2] = Aph[mb+g  ][s*8+tg+4]; ah[mt][3] = Aph[mb+g+8][s*8+tg+4];
                al[mt][0] = Apl[mb+g  ][s*8+tg];   al[mt][1] = Apl[mb+g+8][s*8+tg];
                al[mt][2] = Apl[mb+g  ][s*8+tg+4]; al[mt][3] = Apl[mb+g+8][s*8+tg+4];
            }
#pragma unroll
            for (int nt = 0; nt < 2; nt++) {
                int nr = wn*16 + nt*8 + g;
                unsigned b0h = Bph[nr][s*8+tg], b1h = Bph[nr][s*8+tg+4];
                unsigned b0l = Bpl[nr][s*8+tg], b1l = Bpl[nr][s*8+tg+4];
#pragma unroll
                for (int mt = 0; mt < 2; mt++) {
                    mma_bf16(c[mt][nt], ah[mt], b0h, b1h);
                    mma_bf16(c[mt][nt], ah[mt], b0l, b1l);
                    mma_bf16(c[mt][nt], al[mt], b0h, b1h);
                }
            }
        }
        __syncthreads();
    }
#pragma unroll
    for (int mt = 0; mt < 2; mt++)
#pragma unroll
        for (int nt = 0; nt < 2; nt++) {
            int m = wm*32 + mt*16 + g;
            int n = bn + wn*16 + nt*8 + 2*tg;
            size_t base = ((size_t)ks*128 + m)*D3 + n;
            *(float2*)&g_sp_part[base]                = make_float2(c[mt][nt][0], c[mt][nt][1]);
            *(float2*)&g_sp_part[base + 8*(size_t)D3] = make_float2(c[mt][nt][2], c[mt][nt][3]);
        }
}

// =============== 4a) qm GEMV: qm[b,row] = dot(Wq[row], xm[b]) ===============
// grid 128, 256 threads: warp per row, lane strided, shfl reduce.
__global__ void __launch_bounds__(256)
qm_kernel(const float* __restrict__ Wqkv) {
    __shared__ float sxm[BB*DD];     // 16KB
    const int tid  = threadIdx.x;
    const int w    = tid >> 5;
    const int lane = tid & 31;
#pragma unroll
    for (int i = 0; i < 4; i++)
        ((float4*)sxm)[tid + 256*i] = ((const float4*)g_xm)[tid + 256*i];
    __syncthreads();

    const int row = blockIdx.x * 8 + w;       // 0..1023
    const float4* wr = (const float4*)(Wqkv + (size_t)row*DD);
    float s0 = 0.f, s1 = 0.f, s2 = 0.f, s3 = 0.f;
#pragma unroll
    for (int i = 0; i < 8; i++) {
        float4 wv = wr[lane + 32*i];
        float4 x0 = *(const float4*)&sxm[0*DD + (lane + 32*i)*4];
        float4 x1 = *(const float4*)&sxm[1*DD + (lane + 32*i)*4];
        float4 x2 = *(const float4*)&sxm[2*DD + (lane + 32*i)*4];
        float4 x3 = *(const float4*)&sxm[3*DD + (lane + 32*i)*4];
        s0 += wv.x*x0.x + wv.y*x0.y + wv.z*x0.z + wv.w*x0.w;
        s1 += wv.x*x1.x + wv.y*x1.y + wv.z*x1.z + wv.w*x1.w;
        s2 += wv.x*x2.x + wv.y*x2.y + wv.z*x2.z + wv.w*x2.w;
        s3 += wv.x*x3.x + wv.y*x3.y + wv.z*x3.z + wv.w*x3.w;
    }
#pragma unroll
    for (int off = 16; off > 0; off >>= 1) {
        s0 += __shfl_down_sync(0xffffffffu, s0, off);
        s1 += __shfl_down_sync(0xffffffffu, s1, off);
        s2 += __shfl_down_sync(0xffffffffu, s2, off);
        s3 += __shfl_down_sync(0xffffffffu, s3, off);
    }
    if (lane == 0) {
        g_qm[0*DD + row] = s0;
        g_qm[1*DD + row] = s1;
        g_qm[2*DD + row] = s2;
        g_qm[3*DD + row] = s3;
    }
}

// =============== 4b) fused soliton ODE + pulse MLP (qm precomputed) ==========
// grid 128 x 64 thr. blocks [0,64): soliton (bh=bid); [64,128): pulse MLP
__global__ void ps_kernel(const float* __restrict__ W1, const float* __restrict__ b1,
                          const float* __restrict__ W2, const float* __restrict__ b2,
                          const float* __restrict__ sfilt,
                          const float* __restrict__ pa, const float* __restrict__ pb,
                          float* __restrict__ out_pw, float* __restrict__ out_resp) {
    if (blockIdx.x < 64) {
        // ---- soliton ----
        const int bh = blockIdx.x;
        const int b = bh >> 4, h = bh & 15;
        const int k = threadIdx.x;
        if (k >= 32) return;
        const size_t m = (size_t)(b*KK + k);
        const float* P0 = g_sp_part + m*D3;
        const float* P1 = g_sp_part + (128 + m)*D3;
        float dot = 0.f;
#pragma unroll
        for (int d = 0; d < HDIM/4; d++) {
            float4 q0 = *(const float4*)(P0 + h*HDIM + d*4);
            float4 q1 = *(const float4*)(P1 + h*HDIM + d*4);
            float4 k0 = *(const float4*)(P0 + DD + h*HDIM + d*4);
            float4 k1 = *(const float4*)(P1 + DD + h*HDIM + d*4);
            dot += (q0.x+q1.x)*(k0.x+k1.x) + (q0.y+q1.y)*(k0.y+k1.y)
                 + (q0.z+q1.z)*(k0.z+k1.z) + (q0.w+q1.w)*(k0.w+k1.w);
        }
        float filt = 1.f / (1.f + expf(-sfilt[h*KK + k]));
        float s = dot * 0.125f * filt;

        float scale = fmaxf(fabsf(s), 1e-6f);
        float sn = s / scale;
        float I  = (fabsf(s) > 0.5f) ? sn : 0.1f*sn;
        const float a = *pa, bcoef = *pb;
        const float dt = 0.2f;
        float v = 0.f, w = 0.f;
#pragma unroll
        for (int it = 0; it < 5; it++) {
            float dv = v - v*v*v*(1.f/3.f) - w + I;
            float dw = (v + a - bcoef*w) * 10.f;
            v = fminf(fmaxf(v + dt*dv, -3.f), 3.f);
            w = fminf(fmaxf(w + dt*dw, -3.f), 3.f);
        }
        float r = v * scale;
        g_resp[bh*KK + k]   = r;
        out_resp[bh*KK + k] = r;
    } else {
        // ---- pulse MLP (reads precomputed qm) ----
        __shared__ float qm[HDIM];
        __shared__ float h1[32];
        const int bh = blockIdx.x - 64;
        const int b = bh >> 4, h = bh & 15;
        const int d = threadIdx.x;
        qm[d] = g_qm[(size_t)b*DD + h*HDIM + d];
        __syncthreads();
        if (d < 32) {
            float a = b1[d];
#pragma unroll
            for (int j = 0; j < HDIM; j++) a += qm[j] * W1[d*HDIM + j];
            h1[d] = a / (1.f + expf(-a));
        }
        __syncthreads();
        if (d == 0) {
            float a = b2[0];
#pragma unroll
            for (int j = 0; j < 32; j++) a += h1[j] * W2[j];
            float spl = (a > 20.f) ? a : log1pf(expf(a));
            out_pw[bh] = 4.0f + spl;
        }
    }
}

// =============== 5) M[b] = (resp*v_spec)(32x1024) @ Wout^T, split-K ==========
__global__ void __launch_bounds__(256)
gemmD_kernel(const float* __restrict__ Wout) {
    __shared__ float As[8][32];
    __shared__ float Bs[8][128];
    const int bn = blockIdx.x * 128;
    const int ks = blockIdx.y;
    const int b  = blockIdx.z;
    const int tid = threadIdx.x;
    const int tx = tid & 31;
    const int my = tid >> 5;
    const int lr = tid >> 1, lc = (tid & 1) << 2;

    const float* Bp = Wout + (size_t)(bn + lr)*DD + ks*128 + lc;

    ull acc2[4][2];
#pragma unroll
    for (int i = 0; i < 4; i++) { acc2[i][0] = 0ull; acc2[i][1] = 0ull; }

    for (int k0 = 0; k0 < 128; k0 += 8) {
        if (tid < 64) {
            int ar = tid >> 1, ac = (tid & 1) << 2;
            int col = ks*128 + k0 + ac;
            size_t m = (size_t)(b*KK + ar);
            float4 a0 = *(const float4*)(g_sp_part + m*D3 + 2*DD + col);
            float4 a1 = *(const float4*)(g_sp_part + (128 + m)*D3 + 2*DD + col);
            float r = g_resp[(b*HH + (col >> 6))*KK + ar];
            As[ac+0][ar] = (a0.x + a1.x) * r; As[ac+1][ar] = (a0.y + a1.y) * r;
            As[ac+2][ar] = (a0.z + a1.z) * r; As[ac+3][ar] = (a0.w + a1.w) * r;
        }
        float4 bv = *(const float4*)(Bp + k0);
        Bs[lc+0][lr] = bv.x; Bs[lc+1][lr] = bv.y; Bs[lc+2][lr] = bv.z; Bs[lc+3][lr] = bv.w;
        __syncthreads();
#pragma unroll
        for (int kk = 0; kk < 8; kk++) {
            ulonglong2 rb = *(const ulonglong2*)&Bs[kk][tx*4];
            float a0 = As[kk][my], a1 = As[kk][my+8], a2 = As[kk][my+16], a3 = As[kk][my+24];
            ull p0 = pk2(a0,a0), p1 = pk2(a1,a1), p2 = pk2(a2,a2), p3 = pk2(a3,a3);
            ffma2(acc2[0][0], p0, rb.x); ffma2(acc2[0][1], p0, rb.y);
            ffma2(acc2[1][0], p1, rb.x); ffma2(acc2[1][1], p1, rb.y);
            ffma2(acc2[2][0], p2, rb.x); ffma2(acc2[2][1], p2, rb.y);
            ffma2(acc2[3][0], p3, rb.x); ffma2(acc2[3][1], p3, rb.y);
        }
        __syncthreads();
    }
#pragma unroll
    for (int mi = 0; mi < 4; mi++) {
        int m = my + 8*mi;
        *(ulonglong2*)&g_M_part[(((size_t)ks*BB + b)*KK + m)*DD + bn + tx*4] =
            make_ulonglong2(acc2[mi][0], acc2[mi][1]);
    }
}

__global__ void reduceD_kernel() {
    int gid = blockIdx.x * 256 + threadIdx.x;   // 131072
    float s = 0.f;
#pragma unroll
    for (int ks = 0; ks < KSPL_D; ks++) s += g_M_part[(size_t)ks*131072 + gid];
    g_M[gid] = s;
}

// =============== 6) out[b,t,j] = sum_k basis[b,t,k] * M[b,k,j], tf32 tensor ==
__global__ void __launch_bounds__(256)
out_kernel(const float* __restrict__ basis, float* __restrict__ out) {
    __shared__ float Bh[64][36];
    __shared__ float Bl[64][36];
    __shared__ float Mh[32][72];
    __shared__ float Ml[32][72];
    const int tt = blockIdx.x, jt = blockIdx.y, b = blockIdx.z;
    const int t0 = tt*64, j0 = jt*64;
    const int tid  = threadIdx.x;
    const int w    = tid >> 5;
    const int lane = tid & 31;
    const int g    = lane >> 2;
    const int tg   = lane & 3;
    const int wm   = w >> 2;
    const int wn   = w & 3;

#pragma unroll
    for (int i = 0; i < 2; i++) {
        int f = tid + 256*i;
        int row = f >> 3, c4 = (f & 7) * 4;
        float4 v = *(const float4*)(basis + ((size_t)(b*TT + t0 + row))*KK + c4);
        float hx = tf32_rna(v.x), hy = tf32_rna(v.y), hz = tf32_rna(v.z), hw = tf32_rna(v.w);
        Bh[row][c4+0] = hx; Bh[row][c4+1] = hy; Bh[row][c4+2] = hz; Bh[row][c4+3] = hw;
        Bl[row][c4+0] = v.x - hx; Bl[row][c4+1] = v.y - hy;
        Bl[row][c4+2] = v.z - hz; Bl[row][c4+3] = v.w - hw;
    }
#pragma unroll
    for (int i = 0; i < 2; i++) {
        int f = tid + 256*i;
        int row = f >> 4, c4 = (f & 15) * 4;
        float4 v = *(const float4*)(g_M + ((size_t)b*KK + row)*DD + j0 + c4);
        float hx = tf32_rna(v.x), hy = tf32_rna(v.y), hz = tf32_rna(v.z), hw = tf32_rna(v.w);
        Mh[row][c4+0] = hx; Mh[row][c4+1] = hy; Mh[row][c4+2] = hz; Mh[row][c4+3] = hw;
        Ml[row][c4+0] = v.x - hx; Ml[row][c4+1] = v.y - hy;
        Ml[row][c4+2] = v.z - hz; Ml[row][c4+3] = v.w - hw;
    }
    __syncthreads();

    float c[2][2][4];
#pragma unroll
    for (int i = 0; i < 2; i++)
#pragma unroll
        for (int j = 0; j < 2; j++)
#pragma unroll
            for (int r = 0; r < 4; r++) c[i][j][r] = 0.f;

#pragma unroll
    for (int s = 0; s < 4; s++) {
        const int k0 = s*8 + tg, k1 = s*8 + tg + 4;
        float ah[2][4], al[2][4];
#pragma unroll
        for (int mt = 0; mt < 2; mt++) {
            int mb = wm*32 + mt*16;
            ah[mt][0] = Bh[mb+g][k0];  ah[mt][1] = Bh[mb+g+8][k0];
            ah[mt][2] = Bh[mb+g][k1];  ah[mt][3] = Bh[mb+g+8][k1];
            al[mt][0] = Bl[mb+g][k0];  al[mt][1] = Bl[mb+g+8][k0];
            al[mt][2] = Bl[mb+g][k1];  al[mt][3] = Bl[mb+g+8][k1];
        }
#pragma unroll
        for (int nt = 0; nt < 2; nt++) {
            int nc = wn*16 + nt*8 + g;
            float b0h = Mh[k0][nc], b1h = Mh[k1][nc];
            float b0l = Ml[k0][nc], b1l = Ml[k1][nc];
#pragma unroll
            for (int mt = 0; mt < 2; mt++) {
                mma_tf32(c[mt][nt], ah[mt], b0h, b1h);
                mma_tf32(c[mt][nt], ah[mt], b0l, b1l);
                mma_tf32(c[mt][nt], al[mt], b0h, b1h);
            }
        }
    }
#pragma unroll
    for (int mt = 0; mt < 2; mt++)
#pragma unroll
        for (int nt = 0; nt < 2; nt++) {
            int t = t0 + wm*32 + mt*16 + g;
            int jc = j0 + wn*16 + nt*8 + 2*tg;
            size_t base = ((size_t)b*TT + t)*DD + jc;
            *(float2*)(out + base)                = make_float2(c[mt][nt][0], c[mt][nt][1]);
            *(float2*)(out + base + 8*(size_t)DD) = make_float2(c[mt][nt][2], c[mt][nt][3]);
        }
}

// ---------------- launch ----------------
extern "C" void kernel_launch(void* const* d_in, const int* in_sizes, int n_in,
                              void* d_out, int out_size) {
    const float* x     = (const float*)d_in[0];
    const float* basis = (const float*)d_in[1];
    const float* Wqkv  = (const float*)d_in[2];
    const float* Wout  = (const float*)d_in[3];
    const float* pa    = (const float*)d_in[4];
    const float* pb    = (const float*)d_in[5];
    const float* W1    = (const float*)d_in[6];
    const float* b1    = (const float*)d_in[7];
    const float* W2    = (const float*)d_in[8];
    const float* b2    = (const float*)d_in[9];
    const float* sfilt = (const float*)d_in[10];

    float* out      = (float*)d_out;                 // (B,T,D)
    float* out_pw   = out + (size_t)BB*TT*DD;        // (B,H)
    float* out_resp = out_pw + BH;                   // (B,H,K)

    xs_kernel<<<dim3(BB, 4, TSPLIT), 256>>>(x, basis);
    reduceA_kernel<<<512, 256>>>();
    qm_kernel<<<128, 256>>>(Wqkv);
    gemmB_kernel<<<dim3(96, KSPL_B), 256>>>(Wqkv);
    ps_kernel<<<128, 64>>>(W1, b1, W2, b2, sfilt, pa, pb, out_pw, out_resp);
    gemmD_kernel<<<dim3(8, KSPL_D, BB), 256>>>(Wout);
    reduceD_kernel<<<512, 256>>>();
    out_kernel<<<dim3(64, 16, BB), 256>>>(basis, out);
}